// round 4
// baseline (speedup 1.0000x reference)
#include <cuda_runtime.h>
#include <cuda_bf16.h>
#include <cstdint>
#include <cstddef>

// Problem constants
#define BB 4
#define LL 2048
#define DM 512
#define DI 1024            // D_INNER
#define DS 16              // D_STATE
#define DTR 32             // DT_RANK
#define ML (BB*LL)         // 8192 rows

// ---------------- scratch (no allocations allowed) ----------------
__device__ float g_xz  [(size_t)ML * 2 * DI];
__device__ float g_xc  [(size_t)ML * DI];
__device__ float g_xdbl[(size_t)ML * 64];
__device__ float g_dt  [(size_t)ML * DI];

__device__ __align__(256) __nv_bfloat16 g_xhi [(size_t)ML * DM];
__device__ __align__(256) __nv_bfloat16 g_xlo [(size_t)ML * DM];
__device__ __align__(256) __nv_bfloat16 g_w1hi[(size_t)2 * DI * DM];
__device__ __align__(256) __nv_bfloat16 g_w1lo[(size_t)2 * DI * DM];
__device__ __align__(256) __nv_bfloat16 g_uhi [(size_t)ML * DI];
__device__ __align__(256) __nv_bfloat16 g_ulo [(size_t)ML * DI];
__device__ __align__(256) __nv_bfloat16 g_wxhi[(size_t)64 * DI];
__device__ __align__(256) __nv_bfloat16 g_wxlo[(size_t)64 * DI];
__device__ __align__(256) __nv_bfloat16 g_yhi [(size_t)ML * DI];
__device__ __align__(256) __nv_bfloat16 g_ylo [(size_t)ML * DI];
__device__ __align__(256) __nv_bfloat16 g_w2hi[(size_t)DM * DI];
__device__ __align__(256) __nv_bfloat16 g_w2lo[(size_t)DM * DI];

// ---------------- PTX helpers (base ISA only) ----------------
__device__ __forceinline__ uint32_t smem_u32(const void* p) {
    uint32_t a;
    asm("{ .reg .u64 t; cvta.to.shared.u64 t, %1; cvt.u32.u64 %0, t; }" : "=r"(a) : "l"(p));
    return a;
}
__device__ __forceinline__ void cp_async16(uint32_t saddr, const void* gaddr) {
    asm volatile("cp.async.cg.shared.global [%0], [%1], 16;" :: "r"(saddr), "l"(gaddr));
}
__device__ __forceinline__ void ldm_x4(uint32_t* r, uint32_t addr) {
    asm volatile("ldmatrix.sync.aligned.m8n8.x4.shared.b16 {%0,%1,%2,%3}, [%4];"
                 : "=r"(r[0]), "=r"(r[1]), "=r"(r[2]), "=r"(r[3]) : "r"(addr));
}
__device__ __forceinline__ void ldm_x2(uint32_t* r, uint32_t addr) {
    asm volatile("ldmatrix.sync.aligned.m8n8.x2.shared.b16 {%0,%1}, [%2];"
                 : "=r"(r[0]), "=r"(r[1]) : "r"(addr));
}
__device__ __forceinline__ void mma_bf16(float* d, const uint32_t* a, const uint32_t* b) {
    asm volatile(
        "mma.sync.aligned.m16n8k16.row.col.f32.bf16.bf16.f32 "
        "{%0,%1,%2,%3}, {%4,%5,%6,%7}, {%8,%9}, {%0,%1,%2,%3};"
        : "+f"(d[0]), "+f"(d[1]), "+f"(d[2]), "+f"(d[3])
        : "r"(a[0]), "r"(a[1]), "r"(a[2]), "r"(a[3]), "r"(b[0]), "r"(b[1]));
}
__device__ __forceinline__ float ex2f(float x) {
    float y;
    asm("ex2.approx.f32 %0, %1;" : "=f"(y) : "f"(x));
    return y;
}

// ---------------- math helpers ----------------
__device__ __forceinline__ float softplusf(float x) {
    return (x > 20.f) ? x : log1pf(__expf(x));
}
__device__ __forceinline__ float siluf(float x) {
    return x / (1.f + __expf(-x));
}

// ---------------- fp32 -> bf16 hi/lo split -------------------------
__global__ void cvt_split_kernel(const float* __restrict__ x, __nv_bfloat16* __restrict__ hi,
                                 __nv_bfloat16* __restrict__ lo, int n4) {
    int i = blockIdx.x * 256 + threadIdx.x;
    if (i >= n4) return;
    float4 v = ((const float4*)x)[i];
    __nv_bfloat16 h0 = __float2bfloat16(v.x);
    __nv_bfloat16 h1 = __float2bfloat16(v.y);
    __nv_bfloat16 h2 = __float2bfloat16(v.z);
    __nv_bfloat16 h3 = __float2bfloat16(v.w);
    __nv_bfloat16 l0 = __float2bfloat16(v.x - __bfloat162float(h0));
    __nv_bfloat16 l1 = __float2bfloat16(v.y - __bfloat162float(h1));
    __nv_bfloat16 l2 = __float2bfloat16(v.z - __bfloat162float(h2));
    __nv_bfloat16 l3 = __float2bfloat16(v.w - __bfloat162float(h3));
    __nv_bfloat162 hp0; hp0.x = h0; hp0.y = h1;
    __nv_bfloat162 hp1; hp1.x = h2; hp1.y = h3;
    __nv_bfloat162 lp0; lp0.x = l0; lp0.y = l1;
    __nv_bfloat162 lp1; lp1.x = l2; lp1.y = l3;
    ((__nv_bfloat162*)hi)[i * 2 + 0] = hp0;
    ((__nv_bfloat162*)hi)[i * 2 + 1] = hp1;
    ((__nv_bfloat162*)lo)[i * 2 + 0] = lp0;
    ((__nv_bfloat162*)lo)[i * 2 + 1] = lp1;
}

// ---------------- HMMA split-bf16 GEMM -----------------------------
// C[m,n] = sum_k A[m,k]*W[n,k]; A,W pre-split into bf16 hi/lo.
// CTA tile 128xBN, BK=32, double-buffered cp.async, 8 warps.
#define GPITCH 40                      // smem row pitch in bf16 (32 + 8 pad)

template <int BN>
__global__ __launch_bounds__(256) void mma_gemm_kernel(
    const __nv_bfloat16* __restrict__ Ahi, const __nv_bfloat16* __restrict__ Alo,
    const __nv_bfloat16* __restrict__ Bhi, const __nv_bfloat16* __restrict__ Blo,
    float* __restrict__ C, int K, int ldc) {
    constexpr int NWN = (BN == 128) ? 4 : 2;   // warps along N
    constexpr int NWM = 8 / NWN;               // warps along M
    constexpr int MT = (128 / NWM) / 16;       // 16-row m-tiles per warp
    constexpr int NT = (BN / NWN) / 8;         // 8-col n-tiles per warp
    constexpr int ATB = 128 * GPITCH * 2;      // A tile bytes
    constexpr int BTB = BN * GPITCH * 2;       // B tile bytes
    constexpr int STG = 2 * ATB + 2 * BTB;     // bytes per stage
    constexpr int NSEG = (256 + 2 * BN) * 4;   // 16B segments per stage

    extern __shared__ __align__(128) char smem[];
    const int tid = threadIdx.x;
    const int lane = tid & 31;
    const int wid = tid >> 5;
    const int warp_m = wid / NWN;
    const int warp_n = wid % NWN;
    const int bm = blockIdx.y * 128;
    const int bn = blockIdx.x * BN;

    uint32_t sb = smem_u32(smem);
    const __nv_bfloat16* gp0 = Ahi + (size_t)bm * K;
    const __nv_bfloat16* gp1 = Alo + (size_t)bm * K;
    const __nv_bfloat16* gp2 = Bhi + (size_t)bn * K;
    const __nv_bfloat16* gp3 = Blo + (size_t)bn * K;

    float acc[MT][NT][4];
#pragma unroll
    for (int i = 0; i < MT; i++)
#pragma unroll
        for (int j = 0; j < NT; j++)
#pragma unroll
            for (int v = 0; v < 4; v++) acc[i][j][v] = 0.f;

    const int nch = K >> 5;

    // loader macro-ish: seg -> (tile, row, quad)
#define GLOAD(stage_, k0_)                                                          \
    {                                                                               \
        _Pragma("unroll")                                                           \
        for (int i = 0; i < NSEG / 256; i++) {                                      \
            int seg = tid + i * 256;                                                \
            int q = seg & 3;                                                        \
            uint32_t soff; const __nv_bfloat16* g;                                  \
            if (seg < 1024) {                                                       \
                int t_ = seg >> 9; int r_ = (seg >> 2) & 127;                       \
                soff = t_ * ATB + (r_ * GPITCH + q * 8) * 2;                        \
                g = (t_ == 0 ? gp0 : gp1) + (size_t)r_ * K + (k0_) + q * 8;         \
            } else {                                                                \
                int s2 = seg - 1024; int t_ = s2 / (BN * 4); int r_ = (s2 >> 2) % BN;\
                soff = 2 * ATB + t_ * BTB + (r_ * GPITCH + q * 8) * 2;              \
                g = (t_ == 0 ? gp2 : gp3) + (size_t)r_ * K + (k0_) + q * 8;         \
            }                                                                       \
            cp_async16(sb + (stage_) * STG + soff, g);                              \
        }                                                                           \
        asm volatile("cp.async.commit_group;");                                     \
    }

    GLOAD(0, 0);

    const int arow = warp_m * (MT * 16) + (lane & 15);
    const int acol = (lane >> 4) * 8;
    const int brow = warp_n * (NT * 8) + (lane & 7);
    const int bcol = ((lane >> 3) & 1) * 8;

    for (int c = 0; c < nch; c++) {
        const int s = c & 1;
        if (c + 1 < nch) {
            GLOAD((c + 1) & 1, (c + 1) << 5);
            asm volatile("cp.async.wait_group 1;" ::: "memory");
        } else {
            asm volatile("cp.async.wait_group 0;" ::: "memory");
        }
        __syncthreads();

        uint32_t base = sb + s * STG;
#pragma unroll
        for (int ks = 0; ks < 2; ks++) {
            uint32_t a_hi[MT][4], a_lo[MT][4], b_hi[NT][2], b_lo[NT][2];
#pragma unroll
            for (int im = 0; im < MT; im++) {
                uint32_t off = ((arow + im * 16) * GPITCH + ks * 16 + acol) * 2;
                ldm_x4(a_hi[im], base + 0 * ATB + off);
                ldm_x4(a_lo[im], base + 1 * ATB + off);
            }
#pragma unroll
            for (int jn = 0; jn < NT; jn++) {
                uint32_t off = ((brow + jn * 8) * GPITCH + ks * 16 + bcol) * 2;
                ldm_x2(b_hi[jn], base + 2 * ATB + 0 * BTB + off);
                ldm_x2(b_lo[jn], base + 2 * ATB + 1 * BTB + off);
            }
#pragma unroll
            for (int im = 0; im < MT; im++)
#pragma unroll
                for (int jn = 0; jn < NT; jn++) {
                    mma_bf16(acc[im][jn], a_hi[im], b_hi[jn]);
                    mma_bf16(acc[im][jn], a_hi[im], b_lo[jn]);
                    mma_bf16(acc[im][jn], a_lo[im], b_hi[jn]);
                }
        }
        __syncthreads();
    }
#undef GLOAD

    // epilogue: direct float2 stores
#pragma unroll
    for (int im = 0; im < MT; im++) {
        int r0 = bm + warp_m * (MT * 16) + im * 16 + (lane >> 2);
#pragma unroll
        for (int jn = 0; jn < NT; jn++) {
            int col = bn + warp_n * (NT * 8) + jn * 8 + (lane & 3) * 2;
            float2 v0; v0.x = acc[im][jn][0]; v0.y = acc[im][jn][1];
            float2 v1; v1.x = acc[im][jn][2]; v1.y = acc[im][jn][3];
            *(float2*)(C + (size_t)r0 * ldc + col) = v0;
            *(float2*)(C + (size_t)(r0 + 8) * ldc + col) = v1;
        }
    }
}

#define GSMEM128 (2 * (2 * 128 * GPITCH * 2 + 2 * 128 * GPITCH * 2))  // 81920
#define GSMEM64  (2 * (2 * 128 * GPITCH * 2 + 2 * 64 * GPITCH * 2))   // 61440

// ---------------- SIMT SGEMM (dt GEMM, K=32) -----------------------
template <int ACT>
__global__ void sgemm_kernel(const float* __restrict__ A, const float* __restrict__ W,
                             const float* __restrict__ bias, float* __restrict__ C,
                             int K, int lda, int ldw, int ldc) {
    __shared__ float As[16 * 132];
    __shared__ float Bs[16 * 68];
    const int tid = threadIdx.x;
    const int tx = tid & 15;
    const int ty = tid >> 4;
    const int bm = blockIdx.y * 128;
    const int bn = blockIdx.x * 64;

    const float* Ab = A + (size_t)bm * lda;
    const float* Wb = W + (size_t)bn * ldw;

    float acc[8][4];
#pragma unroll
    for (int i = 0; i < 8; i++)
#pragma unroll
        for (int j = 0; j < 4; j++) acc[i][j] = 0.f;

    for (int k0 = 0; k0 < K; k0 += 16) {
#pragma unroll
        for (int i = 0; i < 2; i++) {
            int qid = tid + i * 256;
            int r = qid >> 2, q = qid & 3;
            float4 v = *(const float4*)(Ab + (size_t)r * lda + k0 + q * 4);
            As[(q * 4 + 0) * 132 + r] = v.x;
            As[(q * 4 + 1) * 132 + r] = v.y;
            As[(q * 4 + 2) * 132 + r] = v.z;
            As[(q * 4 + 3) * 132 + r] = v.w;
        }
        {
            int r = tid >> 2, q = tid & 3;
            float4 v = *(const float4*)(Wb + (size_t)r * ldw + k0 + q * 4);
            Bs[(q * 4 + 0) * 68 + r] = v.x;
            Bs[(q * 4 + 1) * 68 + r] = v.y;
            Bs[(q * 4 + 2) * 68 + r] = v.z;
            Bs[(q * 4 + 3) * 68 + r] = v.w;
        }
        __syncthreads();
#pragma unroll
        for (int k = 0; k < 16; k++) {
            float4 a0 = *(const float4*)(As + k * 132 + ty * 8);
            float4 a1 = *(const float4*)(As + k * 132 + ty * 8 + 4);
            float4 b0 = *(const float4*)(Bs + k * 68 + tx * 4);
            float a[8] = {a0.x, a0.y, a0.z, a0.w, a1.x, a1.y, a1.z, a1.w};
            float bb[4] = {b0.x, b0.y, b0.z, b0.w};
#pragma unroll
            for (int i = 0; i < 8; i++)
#pragma unroll
                for (int j = 0; j < 4; j++) acc[i][j] = fmaf(a[i], bb[j], acc[i][j]);
        }
        __syncthreads();
    }

#pragma unroll
    for (int i = 0; i < 8; i++) {
        int row = bm + ty * 8 + i;
        int col = bn + tx * 4;
        float4 v;
        v.x = acc[i][0]; v.y = acc[i][1]; v.z = acc[i][2]; v.w = acc[i][3];
        if (ACT == 1) {
            v.x = softplusf(v.x + bias[col + 0]);
            v.y = softplusf(v.y + bias[col + 1]);
            v.z = softplusf(v.z + bias[col + 2]);
            v.w = softplusf(v.w + bias[col + 3]);
        }
        *(float4*)(C + (size_t)row * ldc + col) = v;
    }
}

// ------- depthwise causal conv + bias + SiLU; emits fp32 u AND bf16 hi/lo ----
__global__ void conv_silu_kernel(const float* __restrict__ xz, const float* __restrict__ w,
                                 const float* __restrict__ b, float* __restrict__ out,
                                 __nv_bfloat16* __restrict__ uhi, __nv_bfloat16* __restrict__ ulo) {
    int idx = blockIdx.x * 256 + threadIdx.x;
    if (idx >= ML * DI) return;
    int d = idx & (DI - 1);
    int bl = idx >> 10;
    int l = bl & (LL - 1);
    float acc = b[d];
#pragma unroll
    for (int k = 0; k < 4; k++) {
        int lk = l - 3 + k;
        if (lk >= 0) acc = fmaf(w[d * 4 + k], xz[(size_t)(bl - 3 + k) * (2 * DI) + d], acc);
    }
    float s = siluf(acc);
    out[idx] = s;
    __nv_bfloat16 hi = __float2bfloat16(s);
    uhi[idx] = hi;
    ulo[idx] = __float2bfloat16(s - __bfloat162float(hi));
}

// ---------------- selective scan + fused gate, bf16 split output ------------
__global__ void scan_kernel(const float* __restrict__ dtb, const float* __restrict__ ub,
                            const float* __restrict__ xdbl, const float* __restrict__ A_log,
                            const float* __restrict__ xz, const float* __restrict__ Dskip,
                            __nv_bfloat16* __restrict__ yhi, __nv_bfloat16* __restrict__ ylo) {
    int grp = threadIdx.x >> 4;
    int n = threadIdx.x & 15;
    int ch = blockIdx.x * 16 + grp;
    int b = ch >> 10;
    int d = ch & (DI - 1);

    // exp(dt*A) = 2^(dt * A*log2e): fold log2e into An
    float An2 = -__expf(A_log[d * DS + n]) * 1.4426950408889634f;
    float Dd = Dskip[d];

    const float* dtp = dtb + (size_t)b * LL * DI + d;
    const float* up  = ub  + (size_t)b * LL * DI + d;
    const float* bp  = xdbl + (size_t)b * LL * 64 + DTR + n;
    const float* zp  = xz + (size_t)b * LL * 2 * DI + DI + d;
    __nv_bfloat16* yh = yhi + (size_t)b * LL * DI + d;
    __nv_bfloat16* yl = ylo + (size_t)b * LL * DI + d;

    float h = 0.f;
    for (int t = 0; t < LL; t++) {
        float dt = __ldg(dtp + (size_t)t * DI);
        float u  = __ldg(up  + (size_t)t * DI);
        float Bn = __ldg(bp + (size_t)t * 64);
        float Cn = __ldg(bp + (size_t)t * 64 + DS);
        float dA = ex2f(dt * An2);
        h = fmaf(dA, h, dt * u * Bn);
        float p = h * Cn;
        p += __shfl_xor_sync(0xffffffffu, p, 8, 16);
        p += __shfl_xor_sync(0xffffffffu, p, 4, 16);
        p += __shfl_xor_sync(0xffffffffu, p, 2, 16);
        p += __shfl_xor_sync(0xffffffffu, p, 1, 16);
        if (n == 0) {
            float z = __ldg(zp + (size_t)t * 2 * DI);
            float y = fmaf(u, Dd, p) * siluf(z);
            __nv_bfloat16 hi = __float2bfloat16(y);
            yh[(size_t)t * DI] = hi;
            yl[(size_t)t * DI] = __float2bfloat16(y - __bfloat162float(hi));
        }
    }
}

// ---------------- LayerNorm ---------------------------------------
__global__ void ln_kernel(float* __restrict__ io, const float* __restrict__ w,
                          const float* __restrict__ b) {
    __shared__ float ssum[4], ssq[4];
    int row = blockIdx.x;
    float* p = io + (size_t)row * DM;
    int t = threadIdx.x;
    float4 v = ((float4*)p)[t];
    float s = v.x + v.y + v.z + v.w;
    float q = v.x * v.x + v.y * v.y + v.z * v.z + v.w * v.w;
#pragma unroll
    for (int o = 16; o; o >>= 1) {
        s += __shfl_xor_sync(0xffffffffu, s, o);
        q += __shfl_xor_sync(0xffffffffu, q, o);
    }
    if ((t & 31) == 0) { ssum[t >> 5] = s; ssq[t >> 5] = q; }
    __syncthreads();
    s = ssum[0] + ssum[1] + ssum[2] + ssum[3];
    q = ssq[0] + ssq[1] + ssq[2] + ssq[3];
    float mu = s * (1.f / DM);
    float var = q * (1.f / DM) - mu * mu;
    float inv = rsqrtf(var + 1e-5f);
    int c = t * 4;
    float4 o;
    o.x = (v.x - mu) * inv * w[c + 0] + b[c + 0];
    o.y = (v.y - mu) * inv * w[c + 1] + b[c + 1];
    o.z = (v.z - mu) * inv * w[c + 2] + b[c + 2];
    o.w = (v.w - mu) * inv * w[c + 3] + b[c + 3];
    ((float4*)p)[t] = o;
}

// ---------------- launch ------------------------------------------
extern "C" void kernel_launch(void* const* d_in, const int* in_sizes, int n_in,
                              void* d_out, int out_size) {
    const float* x_in      = (const float*)d_in[0];
    const float* in_proj_w = (const float*)d_in[1];
    const float* conv_w    = (const float*)d_in[2];
    const float* conv_b    = (const float*)d_in[3];
    const float* x_proj_w  = (const float*)d_in[4];
    const float* dt_proj_w = (const float*)d_in[5];
    const float* dt_proj_b = (const float*)d_in[6];
    const float* A_log     = (const float*)d_in[7];
    const float* D_skip    = (const float*)d_in[8];
    const float* out_proj_w= (const float*)d_in[9];
    const float* ln_w      = (const float*)d_in[10];
    const float* ln_b      = (const float*)d_in[11];
    float* out = (float*)d_out;

    static float *p_xz=nullptr,*p_xc=nullptr,*p_xdbl=nullptr,*p_dt=nullptr;
    static __nv_bfloat16 *p_xhi,*p_xlo,*p_w1hi,*p_w1lo,*p_uhi,*p_ulo,*p_wxhi,*p_wxlo,
                         *p_yhi,*p_ylo,*p_w2hi,*p_w2lo;
    if (!p_xz) {
        cudaGetSymbolAddress((void**)&p_xz, g_xz);
        cudaGetSymbolAddress((void**)&p_xc, g_xc);
        cudaGetSymbolAddress((void**)&p_xdbl, g_xdbl);
        cudaGetSymbolAddress((void**)&p_dt, g_dt);
        cudaGetSymbolAddress((void**)&p_xhi, g_xhi);
        cudaGetSymbolAddress((void**)&p_xlo, g_xlo);
        cudaGetSymbolAddress((void**)&p_w1hi, g_w1hi);
        cudaGetSymbolAddress((void**)&p_w1lo, g_w1lo);
        cudaGetSymbolAddress((void**)&p_uhi, g_uhi);
        cudaGetSymbolAddress((void**)&p_ulo, g_ulo);
        cudaGetSymbolAddress((void**)&p_wxhi, g_wxhi);
        cudaGetSymbolAddress((void**)&p_wxlo, g_wxlo);
        cudaGetSymbolAddress((void**)&p_yhi, g_yhi);
        cudaGetSymbolAddress((void**)&p_ylo, g_ylo);
        cudaGetSymbolAddress((void**)&p_w2hi, g_w2hi);
        cudaGetSymbolAddress((void**)&p_w2lo, g_w2lo);
        cudaFuncSetAttribute(mma_gemm_kernel<128>, cudaFuncAttributeMaxDynamicSharedMemorySize, GSMEM128);
        cudaFuncSetAttribute(mma_gemm_kernel<64>,  cudaFuncAttributeMaxDynamicSharedMemorySize, GSMEM64);
    }

    // 0) splits of inputs/weights
    cvt_split_kernel<<<(ML * DM / 4) / 256, 256>>>(x_in, p_xhi, p_xlo, ML * DM / 4);
    cvt_split_kernel<<<(2 * DI * DM / 4) / 256, 256>>>(in_proj_w, p_w1hi, p_w1lo, 2 * DI * DM / 4);
    cvt_split_kernel<<<(64 * DI / 4) / 256, 256>>>(x_proj_w, p_wxhi, p_wxlo, 64 * DI / 4);
    cvt_split_kernel<<<(DM * DI / 4) / 256, 256>>>(out_proj_w, p_w2hi, p_w2lo, DM * DI / 4);

    // 1) xz = X @ in_proj_w^T   [8192,2048]  (HMMA)
    mma_gemm_kernel<128><<<dim3(2 * DI / 128, ML / 128), 256, GSMEM128>>>(
        p_xhi, p_xlo, p_w1hi, p_w1lo, p_xz, DM, 2 * DI);

    // 2) u = silu(conv(x)+b)  (+ bf16 split of u)
    conv_silu_kernel<<<(ML * DI) / 256, 256>>>(p_xz, conv_w, conv_b, p_xc, p_uhi, p_ulo);

    // 3) x_dbl = u @ x_proj_w^T   [8192,64]  (HMMA, BN=64)
    mma_gemm_kernel<64><<<dim3(1, ML / 128), 256, GSMEM64>>>(
        p_uhi, p_ulo, p_wxhi, p_wxlo, p_xdbl, DI, 64);

    // 4) dt = softplus(x_dbl[:, :32] @ dt_proj_w^T + b)
    sgemm_kernel<1><<<dim3(DI / 64, ML / 128), 256>>>(p_xdbl, dt_proj_w, dt_proj_b, p_dt, DTR, 64, DTR, DI);

    // 5) selective scan + fused gate -> bf16 hi/lo y
    scan_kernel<<<BB * DI / 16, 256>>>(p_dt, p_xc, p_xdbl, A_log, p_xz, D_skip, p_yhi, p_ylo);

    // 6) out = y @ out_proj_w^T  (HMMA)
    mma_gemm_kernel<128><<<dim3(DM / 128, ML / 128), 256, GSMEM128>>>(
        p_yhi, p_ylo, p_w2hi, p_w2lo, out, DI, DM);

    // 7) LayerNorm in place
    ln_kernel<<<ML, 128>>>(out, ln_w, ln_b);
}

// round 5
// speedup vs baseline: 3.9420x; 3.9420x over previous
#include <cuda_runtime.h>
#include <cuda_bf16.h>
#include <cstdint>
#include <cstddef>

// Problem constants
#define BB 4
#define LL 2048
#define DM 512
#define DI 1024            // D_INNER
#define DS 16              // D_STATE
#define DTR 32             // DT_RANK
#define ML (BB*LL)         // 8192 rows

// ---------------- scratch (no allocations allowed) ----------------
__device__ float g_xz  [(size_t)ML * 2 * DI];
__device__ float g_xc  [(size_t)ML * DI];
__device__ float g_xdbl[(size_t)ML * 64];
__device__ float g_dt  [(size_t)ML * DI];
__device__ float g_ys  [(size_t)ML * DI];

__device__ __align__(256) __nv_bfloat16 g_xhi [(size_t)ML * DM];
__device__ __align__(256) __nv_bfloat16 g_xlo [(size_t)ML * DM];
__device__ __align__(256) __nv_bfloat16 g_w1hi[(size_t)2 * DI * DM];
__device__ __align__(256) __nv_bfloat16 g_w1lo[(size_t)2 * DI * DM];
__device__ __align__(256) __nv_bfloat16 g_uhi [(size_t)ML * DI];
__device__ __align__(256) __nv_bfloat16 g_ulo [(size_t)ML * DI];
__device__ __align__(256) __nv_bfloat16 g_wxhi[(size_t)64 * DI];
__device__ __align__(256) __nv_bfloat16 g_wxlo[(size_t)64 * DI];
__device__ __align__(256) __nv_bfloat16 g_yhi [(size_t)ML * DI];
__device__ __align__(256) __nv_bfloat16 g_ylo [(size_t)ML * DI];
__device__ __align__(256) __nv_bfloat16 g_w2hi[(size_t)DM * DI];
__device__ __align__(256) __nv_bfloat16 g_w2lo[(size_t)DM * DI];

// ---------------- PTX helpers (base ISA only) ----------------
__device__ __forceinline__ uint32_t smem_u32(const void* p) {
    uint32_t a;
    asm("{ .reg .u64 t; cvta.to.shared.u64 t, %1; cvt.u32.u64 %0, t; }" : "=r"(a) : "l"(p));
    return a;
}
__device__ __forceinline__ void cp_async16(uint32_t saddr, const void* gaddr) {
    asm volatile("cp.async.cg.shared.global [%0], [%1], 16;" :: "r"(saddr), "l"(gaddr));
}
__device__ __forceinline__ void ldm_x4(uint32_t* r, uint32_t addr) {
    asm volatile("ldmatrix.sync.aligned.m8n8.x4.shared.b16 {%0,%1,%2,%3}, [%4];"
                 : "=r"(r[0]), "=r"(r[1]), "=r"(r[2]), "=r"(r[3]) : "r"(addr));
}
__device__ __forceinline__ void ldm_x2(uint32_t* r, uint32_t addr) {
    asm volatile("ldmatrix.sync.aligned.m8n8.x2.shared.b16 {%0,%1}, [%2];"
                 : "=r"(r[0]), "=r"(r[1]) : "r"(addr));
}
__device__ __forceinline__ void mma_bf16(float* d, const uint32_t* a, const uint32_t* b) {
    asm volatile(
        "mma.sync.aligned.m16n8k16.row.col.f32.bf16.bf16.f32 "
        "{%0,%1,%2,%3}, {%4,%5,%6,%7}, {%8,%9}, {%0,%1,%2,%3};"
        : "+f"(d[0]), "+f"(d[1]), "+f"(d[2]), "+f"(d[3])
        : "r"(a[0]), "r"(a[1]), "r"(a[2]), "r"(a[3]), "r"(b[0]), "r"(b[1]));
}
__device__ __forceinline__ float ex2f(float x) {
    float y;
    asm("ex2.approx.f32 %0, %1;" : "=f"(y) : "f"(x));
    return y;
}

// ---------------- math helpers ----------------
__device__ __forceinline__ float softplusf(float x) {
    return (x > 20.f) ? x : log1pf(__expf(x));
}
__device__ __forceinline__ float siluf(float x) {
    return x * __frcp_rn(1.f + __expf(-x));
}

// ---------------- fp32 -> bf16 hi/lo split -------------------------
__global__ void cvt_split_kernel(const float* __restrict__ x, __nv_bfloat16* __restrict__ hi,
                                 __nv_bfloat16* __restrict__ lo, int n4) {
    int i = blockIdx.x * 256 + threadIdx.x;
    if (i >= n4) return;
    float4 v = ((const float4*)x)[i];
    __nv_bfloat16 h0 = __float2bfloat16(v.x);
    __nv_bfloat16 h1 = __float2bfloat16(v.y);
    __nv_bfloat16 h2 = __float2bfloat16(v.z);
    __nv_bfloat16 h3 = __float2bfloat16(v.w);
    __nv_bfloat16 l0 = __float2bfloat16(v.x - __bfloat162float(h0));
    __nv_bfloat16 l1 = __float2bfloat16(v.y - __bfloat162float(h1));
    __nv_bfloat16 l2 = __float2bfloat16(v.z - __bfloat162float(h2));
    __nv_bfloat16 l3 = __float2bfloat16(v.w - __bfloat162float(h3));
    __nv_bfloat162 hp0; hp0.x = h0; hp0.y = h1;
    __nv_bfloat162 hp1; hp1.x = h2; hp1.y = h3;
    __nv_bfloat162 lp0; lp0.x = l0; lp0.y = l1;
    __nv_bfloat162 lp1; lp1.x = l2; lp1.y = l3;
    ((__nv_bfloat162*)hi)[i * 2 + 0] = hp0;
    ((__nv_bfloat162*)hi)[i * 2 + 1] = hp1;
    ((__nv_bfloat162*)lo)[i * 2 + 0] = lp0;
    ((__nv_bfloat162*)lo)[i * 2 + 1] = lp1;
}

// ---------------- HMMA split-bf16 GEMM -----------------------------
#define GPITCH 40                      // smem row pitch in bf16 (32 + 8 pad)

template <int BN>
__global__ __launch_bounds__(256) void mma_gemm_kernel(
    const __nv_bfloat16* __restrict__ Ahi, const __nv_bfloat16* __restrict__ Alo,
    const __nv_bfloat16* __restrict__ Bhi, const __nv_bfloat16* __restrict__ Blo,
    float* __restrict__ C, int K, int ldc) {
    constexpr int NWN = (BN == 128) ? 4 : 2;   // warps along N
    constexpr int NWM = 8 / NWN;               // warps along M
    constexpr int MT = (128 / NWM) / 16;       // 16-row m-tiles per warp
    constexpr int NT = (BN / NWN) / 8;         // 8-col n-tiles per warp
    constexpr int ATB = 128 * GPITCH * 2;      // A tile bytes
    constexpr int BTB = BN * GPITCH * 2;       // B tile bytes
    constexpr int STG = 2 * ATB + 2 * BTB;     // bytes per stage
    constexpr int NSEG = (256 + 2 * BN) * 4;   // 16B segments per stage

    extern __shared__ __align__(128) char smem[];
    const int tid = threadIdx.x;
    const int lane = tid & 31;
    const int wid = tid >> 5;
    const int warp_m = wid / NWN;
    const int warp_n = wid % NWN;
    const int bm = blockIdx.y * 128;
    const int bn = blockIdx.x * BN;

    uint32_t sb = smem_u32(smem);
    const __nv_bfloat16* gp0 = Ahi + (size_t)bm * K;
    const __nv_bfloat16* gp1 = Alo + (size_t)bm * K;
    const __nv_bfloat16* gp2 = Bhi + (size_t)bn * K;
    const __nv_bfloat16* gp3 = Blo + (size_t)bn * K;

    float acc[MT][NT][4];
#pragma unroll
    for (int i = 0; i < MT; i++)
#pragma unroll
        for (int j = 0; j < NT; j++)
#pragma unroll
            for (int v = 0; v < 4; v++) acc[i][j][v] = 0.f;

    const int nch = K >> 5;

#define GLOAD(stage_, k0_)                                                          \
    {                                                                               \
        _Pragma("unroll")                                                           \
        for (int i = 0; i < NSEG / 256; i++) {                                      \
            int seg = tid + i * 256;                                                \
            int q = seg & 3;                                                        \
            uint32_t soff; const __nv_bfloat16* g;                                  \
            if (seg < 1024) {                                                       \
                int t_ = seg >> 9; int r_ = (seg >> 2) & 127;                       \
                soff = t_ * ATB + (r_ * GPITCH + q * 8) * 2;                        \
                g = (t_ == 0 ? gp0 : gp1) + (size_t)r_ * K + (k0_) + q * 8;         \
            } else {                                                                \
                int s2 = seg - 1024; int t_ = s2 / (BN * 4); int r_ = (s2 >> 2) % BN;\
                soff = 2 * ATB + t_ * BTB + (r_ * GPITCH + q * 8) * 2;              \
                g = (t_ == 0 ? gp2 : gp3) + (size_t)r_ * K + (k0_) + q * 8;         \
            }                                                                       \
            cp_async16(sb + (stage_) * STG + soff, g);                              \
        }                                                                           \
        asm volatile("cp.async.commit_group;");                                     \
    }

    GLOAD(0, 0);

    const int arow = warp_m * (MT * 16) + (lane & 15);
    const int acol = (lane >> 4) * 8;
    const int brow = warp_n * (NT * 8) + (lane & 7);
    const int bcol = ((lane >> 3) & 1) * 8;

    for (int c = 0; c < nch; c++) {
        const int s = c & 1;
        if (c + 1 < nch) {
            GLOAD((c + 1) & 1, (c + 1) << 5);
            asm volatile("cp.async.wait_group 1;" ::: "memory");
        } else {
            asm volatile("cp.async.wait_group 0;" ::: "memory");
        }
        __syncthreads();

        uint32_t base = sb + s * STG;
#pragma unroll
        for (int ks = 0; ks < 2; ks++) {
            uint32_t a_hi[MT][4], a_lo[MT][4], b_hi[NT][2], b_lo[NT][2];
#pragma unroll
            for (int im = 0; im < MT; im++) {
                uint32_t off = ((arow + im * 16) * GPITCH + ks * 16 + acol) * 2;
                ldm_x4(a_hi[im], base + 0 * ATB + off);
                ldm_x4(a_lo[im], base + 1 * ATB + off);
            }
#pragma unroll
            for (int jn = 0; jn < NT; jn++) {
                uint32_t off = ((brow + jn * 8) * GPITCH + ks * 16 + bcol) * 2;
                ldm_x2(b_hi[jn], base + 2 * ATB + 0 * BTB + off);
                ldm_x2(b_lo[jn], base + 2 * ATB + 1 * BTB + off);
            }
#pragma unroll
            for (int im = 0; im < MT; im++)
#pragma unroll
                for (int jn = 0; jn < NT; jn++) {
                    mma_bf16(acc[im][jn], a_hi[im], b_hi[jn]);
                    mma_bf16(acc[im][jn], a_hi[im], b_lo[jn]);
                    mma_bf16(acc[im][jn], a_lo[im], b_hi[jn]);
                }
        }
        __syncthreads();
    }
#undef GLOAD

#pragma unroll
    for (int im = 0; im < MT; im++) {
        int r0 = bm + warp_m * (MT * 16) + im * 16 + (lane >> 2);
#pragma unroll
        for (int jn = 0; jn < NT; jn++) {
            int col = bn + warp_n * (NT * 8) + jn * 8 + (lane & 3) * 2;
            float2 v0; v0.x = acc[im][jn][0]; v0.y = acc[im][jn][1];
            float2 v1; v1.x = acc[im][jn][2]; v1.y = acc[im][jn][3];
            *(float2*)(C + (size_t)r0 * ldc + col) = v0;
            *(float2*)(C + (size_t)(r0 + 8) * ldc + col) = v1;
        }
    }
}

#define GSMEM128 (2 * (2 * 128 * GPITCH * 2 + 2 * 128 * GPITCH * 2))  // 81920
#define GSMEM64  (2 * (2 * 128 * GPITCH * 2 + 2 * 64 * GPITCH * 2))   // 61440

// ---------------- SIMT SGEMM (dt GEMM, K=32) -----------------------
template <int ACT>
__global__ void sgemm_kernel(const float* __restrict__ A, const float* __restrict__ W,
                             const float* __restrict__ bias, float* __restrict__ C,
                             int K, int lda, int ldw, int ldc) {
    __shared__ float As[16 * 132];
    __shared__ float Bs[16 * 68];
    const int tid = threadIdx.x;
    const int tx = tid & 15;
    const int ty = tid >> 4;
    const int bm = blockIdx.y * 128;
    const int bn = blockIdx.x * 64;

    const float* Ab = A + (size_t)bm * lda;
    const float* Wb = W + (size_t)bn * ldw;

    float acc[8][4];
#pragma unroll
    for (int i = 0; i < 8; i++)
#pragma unroll
        for (int j = 0; j < 4; j++) acc[i][j] = 0.f;

    for (int k0 = 0; k0 < K; k0 += 16) {
#pragma unroll
        for (int i = 0; i < 2; i++) {
            int qid = tid + i * 256;
            int r = qid >> 2, q = qid & 3;
            float4 v = *(const float4*)(Ab + (size_t)r * lda + k0 + q * 4);
            As[(q * 4 + 0) * 132 + r] = v.x;
            As[(q * 4 + 1) * 132 + r] = v.y;
            As[(q * 4 + 2) * 132 + r] = v.z;
            As[(q * 4 + 3) * 132 + r] = v.w;
        }
        {
            int r = tid >> 2, q = tid & 3;
            float4 v = *(const float4*)(Wb + (size_t)r * ldw + k0 + q * 4);
            Bs[(q * 4 + 0) * 68 + r] = v.x;
            Bs[(q * 4 + 1) * 68 + r] = v.y;
            Bs[(q * 4 + 2) * 68 + r] = v.z;
            Bs[(q * 4 + 3) * 68 + r] = v.w;
        }
        __syncthreads();
#pragma unroll
        for (int k = 0; k < 16; k++) {
            float4 a0 = *(const float4*)(As + k * 132 + ty * 8);
            float4 a1 = *(const float4*)(As + k * 132 + ty * 8 + 4);
            float4 b0 = *(const float4*)(Bs + k * 68 + tx * 4);
            float a[8] = {a0.x, a0.y, a0.z, a0.w, a1.x, a1.y, a1.z, a1.w};
            float bb[4] = {b0.x, b0.y, b0.z, b0.w};
#pragma unroll
            for (int i = 0; i < 8; i++)
#pragma unroll
                for (int j = 0; j < 4; j++) acc[i][j] = fmaf(a[i], bb[j], acc[i][j]);
        }
        __syncthreads();
    }

#pragma unroll
    for (int i = 0; i < 8; i++) {
        int row = bm + ty * 8 + i;
        int col = bn + tx * 4;
        float4 v;
        v.x = acc[i][0]; v.y = acc[i][1]; v.z = acc[i][2]; v.w = acc[i][3];
        if (ACT == 1) {
            v.x = softplusf(v.x + bias[col + 0]);
            v.y = softplusf(v.y + bias[col + 1]);
            v.z = softplusf(v.z + bias[col + 2]);
            v.w = softplusf(v.w + bias[col + 3]);
        }
        *(float4*)(C + (size_t)row * ldc + col) = v;
    }
}

// ------- depthwise causal conv + bias + SiLU; emits fp32 u AND bf16 hi/lo ----
__global__ void conv_silu_kernel(const float* __restrict__ xz, const float* __restrict__ w,
                                 const float* __restrict__ b, float* __restrict__ out,
                                 __nv_bfloat16* __restrict__ uhi, __nv_bfloat16* __restrict__ ulo) {
    int idx = blockIdx.x * 256 + threadIdx.x;
    if (idx >= ML * DI) return;
    int d = idx & (DI - 1);
    int bl = idx >> 10;
    int l = bl & (LL - 1);
    float acc = b[d];
#pragma unroll
    for (int k = 0; k < 4; k++) {
        int lk = l - 3 + k;
        if (lk >= 0) acc = fmaf(w[d * 4 + k], xz[(size_t)(bl - 3 + k) * (2 * DI) + d], acc);
    }
    float s = siluf(acc);
    out[idx] = s;
    __nv_bfloat16 hi = __float2bfloat16(s);
    uhi[idx] = hi;
    ulo[idx] = __float2bfloat16(s - __bfloat162float(hi));
}

// ------- selective scan, explicit software pipelining (unroll 8 + prefetch) --
#define SU 8
__global__ void scan_kernel(const float* __restrict__ dtb, const float* __restrict__ ub,
                            const float* __restrict__ xdbl, const float* __restrict__ A_log,
                            float* __restrict__ ys) {
    int grp = threadIdx.x >> 4;
    int n = threadIdx.x & 15;
    int ch = blockIdx.x * 16 + grp;
    int b = ch >> 10;
    int d = ch & (DI - 1);

    float An2 = -__expf(A_log[d * DS + n]) * 1.4426950408889634f;

    const float* dtp = dtb + (size_t)b * LL * DI + d;
    const float* up  = ub  + (size_t)b * LL * DI + d;
    const float* bp  = xdbl + (size_t)b * LL * 64 + DTR + n;
    float* yp = ys + (size_t)b * LL * DI + d;

    float h = 0.f;
    float cdt[SU], cu[SU], cB[SU], cC[SU];
#pragma unroll
    for (int j = 0; j < SU; j++) {
        cdt[j] = __ldg(dtp + (size_t)j * DI);
        cu[j]  = __ldg(up + (size_t)j * DI);
        cB[j]  = __ldg(bp + (size_t)j * 64);
        cC[j]  = __ldg(bp + (size_t)j * 64 + DS);
    }
    for (int t0 = 0; t0 < LL; t0 += SU) {
        float ndt[SU], nu[SU], nB[SU], nC[SU];
        if (t0 + SU < LL) {
#pragma unroll
            for (int j = 0; j < SU; j++) {
                size_t o = (size_t)(t0 + SU + j);
                ndt[j] = __ldg(dtp + o * DI);
                nu[j]  = __ldg(up + o * DI);
                nB[j]  = __ldg(bp + o * 64);
                nC[j]  = __ldg(bp + o * 64 + DS);
            }
        }
#pragma unroll
        for (int j = 0; j < SU; j++) {
            float dA = ex2f(cdt[j] * An2);
            h = fmaf(dA, h, cdt[j] * cu[j] * cB[j]);
            float p = h * cC[j];
            p += __shfl_xor_sync(0xffffffffu, p, 8, 16);
            p += __shfl_xor_sync(0xffffffffu, p, 4, 16);
            p += __shfl_xor_sync(0xffffffffu, p, 2, 16);
            p += __shfl_xor_sync(0xffffffffu, p, 1, 16);
            if (n == 0) yp[(size_t)(t0 + j) * DI] = p;
        }
#pragma unroll
        for (int j = 0; j < SU; j++) {
            cdt[j] = ndt[j]; cu[j] = nu[j]; cB[j] = nB[j]; cC[j] = nC[j];
        }
    }
}

// ------- gate + bf16 split: y = (ys + u*D) * silu(z) -> hi/lo -----------------
__global__ void gate_split_kernel(const float* __restrict__ ys, const float* __restrict__ u,
                                  const float* __restrict__ xz, const float* __restrict__ Dskip,
                                  __nv_bfloat16* __restrict__ yhi, __nv_bfloat16* __restrict__ ylo) {
    int idx = blockIdx.x * 256 + threadIdx.x;
    if (idx >= ML * DI) return;
    int d = idx & (DI - 1);
    size_t bl = (size_t)(idx >> 10);
    float z = xz[bl * (2 * DI) + DI + d];
    float y = fmaf(u[idx], Dskip[d], ys[idx]) * siluf(z);
    __nv_bfloat16 hi = __float2bfloat16(y);
    yhi[idx] = hi;
    ylo[idx] = __float2bfloat16(y - __bfloat162float(hi));
}

// ---------------- LayerNorm ---------------------------------------
__global__ void ln_kernel(float* __restrict__ io, const float* __restrict__ w,
                          const float* __restrict__ b) {
    __shared__ float ssum[4], ssq[4];
    int row = blockIdx.x;
    float* p = io + (size_t)row * DM;
    int t = threadIdx.x;
    float4 v = ((float4*)p)[t];
    float s = v.x + v.y + v.z + v.w;
    float q = v.x * v.x + v.y * v.y + v.z * v.z + v.w * v.w;
#pragma unroll
    for (int o = 16; o; o >>= 1) {
        s += __shfl_xor_sync(0xffffffffu, s, o);
        q += __shfl_xor_sync(0xffffffffu, q, o);
    }
    if ((t & 31) == 0) { ssum[t >> 5] = s; ssq[t >> 5] = q; }
    __syncthreads();
    s = ssum[0] + ssum[1] + ssum[2] + ssum[3];
    q = ssq[0] + ssq[1] + ssq[2] + ssq[3];
    float mu = s * (1.f / DM);
    float var = q * (1.f / DM) - mu * mu;
    float inv = rsqrtf(var + 1e-5f);
    int c = t * 4;
    float4 o;
    o.x = (v.x - mu) * inv * w[c + 0] + b[c + 0];
    o.y = (v.y - mu) * inv * w[c + 1] + b[c + 1];
    o.z = (v.z - mu) * inv * w[c + 2] + b[c + 2];
    o.w = (v.w - mu) * inv * w[c + 3] + b[c + 3];
    ((float4*)p)[t] = o;
}

// ---------------- launch ------------------------------------------
extern "C" void kernel_launch(void* const* d_in, const int* in_sizes, int n_in,
                              void* d_out, int out_size) {
    const float* x_in      = (const float*)d_in[0];
    const float* in_proj_w = (const float*)d_in[1];
    const float* conv_w    = (const float*)d_in[2];
    const float* conv_b    = (const float*)d_in[3];
    const float* x_proj_w  = (const float*)d_in[4];
    const float* dt_proj_w = (const float*)d_in[5];
    const float* dt_proj_b = (const float*)d_in[6];
    const float* A_log     = (const float*)d_in[7];
    const float* D_skip    = (const float*)d_in[8];
    const float* out_proj_w= (const float*)d_in[9];
    const float* ln_w      = (const float*)d_in[10];
    const float* ln_b      = (const float*)d_in[11];
    float* out = (float*)d_out;

    static float *p_xz=nullptr,*p_xc=nullptr,*p_xdbl=nullptr,*p_dt=nullptr,*p_ys=nullptr;
    static __nv_bfloat16 *p_xhi,*p_xlo,*p_w1hi,*p_w1lo,*p_uhi,*p_ulo,*p_wxhi,*p_wxlo,
                         *p_yhi,*p_ylo,*p_w2hi,*p_w2lo;
    if (!p_xz) {
        cudaGetSymbolAddress((void**)&p_xz, g_xz);
        cudaGetSymbolAddress((void**)&p_xc, g_xc);
        cudaGetSymbolAddress((void**)&p_xdbl, g_xdbl);
        cudaGetSymbolAddress((void**)&p_dt, g_dt);
        cudaGetSymbolAddress((void**)&p_ys, g_ys);
        cudaGetSymbolAddress((void**)&p_xhi, g_xhi);
        cudaGetSymbolAddress((void**)&p_xlo, g_xlo);
        cudaGetSymbolAddress((void**)&p_w1hi, g_w1hi);
        cudaGetSymbolAddress((void**)&p_w1lo, g_w1lo);
        cudaGetSymbolAddress((void**)&p_uhi, g_uhi);
        cudaGetSymbolAddress((void**)&p_ulo, g_ulo);
        cudaGetSymbolAddress((void**)&p_wxhi, g_wxhi);
        cudaGetSymbolAddress((void**)&p_wxlo, g_wxlo);
        cudaGetSymbolAddress((void**)&p_yhi, g_yhi);
        cudaGetSymbolAddress((void**)&p_ylo, g_ylo);
        cudaGetSymbolAddress((void**)&p_w2hi, g_w2hi);
        cudaGetSymbolAddress((void**)&p_w2lo, g_w2lo);
        cudaFuncSetAttribute(mma_gemm_kernel<128>, cudaFuncAttributeMaxDynamicSharedMemorySize, GSMEM128);
        cudaFuncSetAttribute(mma_gemm_kernel<64>,  cudaFuncAttributeMaxDynamicSharedMemorySize, GSMEM64);
    }

    // 0) splits of inputs/weights
    cvt_split_kernel<<<(ML * DM / 4) / 256, 256>>>(x_in, p_xhi, p_xlo, ML * DM / 4);
    cvt_split_kernel<<<(2 * DI * DM / 4) / 256, 256>>>(in_proj_w, p_w1hi, p_w1lo, 2 * DI * DM / 4);
    cvt_split_kernel<<<(64 * DI / 4) / 256, 256>>>(x_proj_w, p_wxhi, p_wxlo, 64 * DI / 4);
    cvt_split_kernel<<<(DM * DI / 4) / 256, 256>>>(out_proj_w, p_w2hi, p_w2lo, DM * DI / 4);

    // 1) xz = X @ in_proj_w^T   [8192,2048]  (HMMA)
    mma_gemm_kernel<128><<<dim3(2 * DI / 128, ML / 128), 256, GSMEM128>>>(
        p_xhi, p_xlo, p_w1hi, p_w1lo, p_xz, DM, 2 * DI);

    // 2) u = silu(conv(x)+b)  (+ bf16 split of u)
    conv_silu_kernel<<<(ML * DI) / 256, 256>>>(p_xz, conv_w, conv_b, p_xc, p_uhi, p_ulo);

    // 3) x_dbl = u @ x_proj_w^T   [8192,64]  (HMMA, BN=64)
    mma_gemm_kernel<64><<<dim3(1, ML / 128), 256, GSMEM64>>>(
        p_uhi, p_ulo, p_wxhi, p_wxlo, p_xdbl, DI, 64);

    // 4) dt = softplus(x_dbl[:, :32] @ dt_proj_w^T + b)
    sgemm_kernel<1><<<dim3(DI / 64, ML / 128), 256>>>(p_xdbl, dt_proj_w, dt_proj_b, p_dt, DTR, 64, DTR, DI);

    // 5) selective scan (explicitly pipelined)
    scan_kernel<<<BB * DI / 16, 256>>>(p_dt, p_xc, p_xdbl, A_log, p_ys);

    // 6) gate + bf16 split of y
    gate_split_kernel<<<(ML * DI) / 256, 256>>>(p_ys, p_xc, p_xz, D_skip, p_yhi, p_ylo);

    // 7) out = y @ out_proj_w^T  (HMMA)
    mma_gemm_kernel<128><<<dim3(DM / 128, ML / 128), 256, GSMEM128>>>(
        p_yhi, p_ylo, p_w2hi, p_w2lo, out, DI, DM);

    // 8) LayerNorm in place
    ln_kernel<<<ML, 128>>>(out, ln_w, ln_b);
}

// round 6
// speedup vs baseline: 4.4579x; 1.1309x over previous
#include <cuda_runtime.h>
#include <cuda_bf16.h>
#include <cstdint>
#include <cstddef>

// Problem constants
#define BB 4
#define LL 2048
#define DM 512
#define DI 1024            // D_INNER
#define DS 16              // D_STATE
#define DTR 32             // DT_RANK
#define ML (BB*LL)         // 8192 rows

// ---------------- scratch (no allocations allowed) ----------------
__device__ float g_xz  [(size_t)ML * 2 * DI];
__device__ float g_xc  [(size_t)ML * DI];
__device__ float g_xdbl[(size_t)ML * 64];
__device__ float g_dt  [(size_t)ML * DI];
__device__ float g_ys  [(size_t)ML * DI];

__device__ __align__(256) __nv_bfloat16 g_xhi [(size_t)ML * DM];
__device__ __align__(256) __nv_bfloat16 g_xlo [(size_t)ML * DM];
__device__ __align__(256) __nv_bfloat16 g_w1hi[(size_t)2 * DI * DM];
__device__ __align__(256) __nv_bfloat16 g_w1lo[(size_t)2 * DI * DM];
__device__ __align__(256) __nv_bfloat16 g_uhi [(size_t)ML * DI];
__device__ __align__(256) __nv_bfloat16 g_ulo [(size_t)ML * DI];
__device__ __align__(256) __nv_bfloat16 g_wxhi[(size_t)64 * DI];
__device__ __align__(256) __nv_bfloat16 g_wxlo[(size_t)64 * DI];
__device__ __align__(256) __nv_bfloat16 g_yhi [(size_t)ML * DI];
__device__ __align__(256) __nv_bfloat16 g_ylo [(size_t)ML * DI];
__device__ __align__(256) __nv_bfloat16 g_w2hi[(size_t)DM * DI];
__device__ __align__(256) __nv_bfloat16 g_w2lo[(size_t)DM * DI];

// ---------------- PTX helpers (base ISA only) ----------------
__device__ __forceinline__ uint32_t smem_u32(const void* p) {
    uint32_t a;
    asm("{ .reg .u64 t; cvta.to.shared.u64 t, %1; cvt.u32.u64 %0, t; }" : "=r"(a) : "l"(p));
    return a;
}
__device__ __forceinline__ void cp_async16(uint32_t saddr, const void* gaddr) {
    asm volatile("cp.async.cg.shared.global [%0], [%1], 16;" :: "r"(saddr), "l"(gaddr));
}
__device__ __forceinline__ void ldm_x4(uint32_t* r, uint32_t addr) {
    asm volatile("ldmatrix.sync.aligned.m8n8.x4.shared.b16 {%0,%1,%2,%3}, [%4];"
                 : "=r"(r[0]), "=r"(r[1]), "=r"(r[2]), "=r"(r[3]) : "r"(addr));
}
__device__ __forceinline__ void ldm_x2(uint32_t* r, uint32_t addr) {
    asm volatile("ldmatrix.sync.aligned.m8n8.x2.shared.b16 {%0,%1}, [%2];"
                 : "=r"(r[0]), "=r"(r[1]) : "r"(addr));
}
__device__ __forceinline__ void mma_bf16(float* d, const uint32_t* a, const uint32_t* b) {
    asm volatile(
        "mma.sync.aligned.m16n8k16.row.col.f32.bf16.bf16.f32 "
        "{%0,%1,%2,%3}, {%4,%5,%6,%7}, {%8,%9}, {%0,%1,%2,%3};"
        : "+f"(d[0]), "+f"(d[1]), "+f"(d[2]), "+f"(d[3])
        : "r"(a[0]), "r"(a[1]), "r"(a[2]), "r"(a[3]), "r"(b[0]), "r"(b[1]));
}
__device__ __forceinline__ float ex2f(float x) {
    float y;
    asm("ex2.approx.f32 %0, %1;" : "=f"(y) : "f"(x));
    return y;
}
// XOR swizzle for 64B rows: conflict-free for 16B cp.async writes + ldmatrix
__device__ __forceinline__ uint32_t sw64(uint32_t o) { return o ^ ((o >> 3) & 0x30); }

// ---------------- math helpers ----------------
__device__ __forceinline__ float softplusf(float x) {
    return (x > 20.f) ? x : log1pf(__expf(x));
}
__device__ __forceinline__ float siluf(float x) {
    return x * __frcp_rn(1.f + __expf(-x));
}

// ---------------- fp32 -> bf16 hi/lo split -------------------------
__global__ void cvt_split_kernel(const float* __restrict__ x, __nv_bfloat16* __restrict__ hi,
                                 __nv_bfloat16* __restrict__ lo, int n4) {
    int i = blockIdx.x * 256 + threadIdx.x;
    if (i >= n4) return;
    float4 v = ((const float4*)x)[i];
    __nv_bfloat16 h0 = __float2bfloat16(v.x);
    __nv_bfloat16 h1 = __float2bfloat16(v.y);
    __nv_bfloat16 h2 = __float2bfloat16(v.z);
    __nv_bfloat16 h3 = __float2bfloat16(v.w);
    __nv_bfloat16 l0 = __float2bfloat16(v.x - __bfloat162float(h0));
    __nv_bfloat16 l1 = __float2bfloat16(v.y - __bfloat162float(h1));
    __nv_bfloat16 l2 = __float2bfloat16(v.z - __bfloat162float(h2));
    __nv_bfloat16 l3 = __float2bfloat16(v.w - __bfloat162float(h3));
    __nv_bfloat162 hp0; hp0.x = h0; hp0.y = h1;
    __nv_bfloat162 hp1; hp1.x = h2; hp1.y = h3;
    __nv_bfloat162 lp0; lp0.x = l0; lp0.y = l1;
    __nv_bfloat162 lp1; lp1.x = l2; lp1.y = l3;
    ((__nv_bfloat162*)hi)[i * 2 + 0] = hp0;
    ((__nv_bfloat162*)hi)[i * 2 + 1] = hp1;
    ((__nv_bfloat162*)lo)[i * 2 + 0] = lp0;
    ((__nv_bfloat162*)lo)[i * 2 + 1] = lp1;
}

// ---------------- HMMA split-bf16 GEMM -----------------------------
// 64B rows (BK=32 bf16), XOR-swizzled, 3-stage cp.async pipeline.
template <int BN>
__global__ __launch_bounds__(256) void mma_gemm_kernel(
    const __nv_bfloat16* __restrict__ Ahi, const __nv_bfloat16* __restrict__ Alo,
    const __nv_bfloat16* __restrict__ Bhi, const __nv_bfloat16* __restrict__ Blo,
    float* __restrict__ C, int K, int ldc) {
    constexpr int NWN = (BN == 128) ? 4 : 2;   // warps along N
    constexpr int NWM = 8 / NWN;               // warps along M
    constexpr int MT = (128 / NWM) / 16;       // 16-row m-tiles per warp
    constexpr int NT = (BN / NWN) / 8;         // 8-col n-tiles per warp
    constexpr int ATB = 128 * 64;              // A tile bytes (128 rows x 64B)
    constexpr int BTB = BN * 64;               // B tile bytes
    constexpr int STG = 2 * ATB + 2 * BTB;     // bytes per stage
    constexpr int NSEG = (256 + 2 * BN) * 4;   // 16B segments per stage

    extern __shared__ __align__(128) char smem[];
    const int tid = threadIdx.x;
    const int lane = tid & 31;
    const int wid = tid >> 5;
    const int warp_m = wid / NWN;
    const int warp_n = wid % NWN;
    const int bm = blockIdx.y * 128;
    const int bn = blockIdx.x * BN;

    uint32_t sb = smem_u32(smem);
    const __nv_bfloat16* gp0 = Ahi + (size_t)bm * K;
    const __nv_bfloat16* gp1 = Alo + (size_t)bm * K;
    const __nv_bfloat16* gp2 = Bhi + (size_t)bn * K;
    const __nv_bfloat16* gp3 = Blo + (size_t)bn * K;

    float acc[MT][NT][4];
#pragma unroll
    for (int i = 0; i < MT; i++)
#pragma unroll
        for (int j = 0; j < NT; j++)
#pragma unroll
            for (int v = 0; v < 4; v++) acc[i][j][v] = 0.f;

    const int nch = K >> 5;

#define GLOAD(stage_, k0_)                                                          \
    {                                                                               \
        _Pragma("unroll")                                                           \
        for (int i = 0; i < NSEG / 256; i++) {                                      \
            int seg = tid + i * 256;                                                \
            int q = seg & 3;                                                        \
            uint32_t soff; const __nv_bfloat16* g;                                  \
            if (seg < 1024) {                                                       \
                int t_ = seg >> 9; int r_ = (seg >> 2) & 127;                       \
                soff = t_ * ATB + sw64(r_ * 64 + q * 16);                           \
                g = (t_ == 0 ? gp0 : gp1) + (size_t)r_ * K + (k0_) + q * 8;         \
            } else {                                                                \
                int s2 = seg - 1024; int t_ = s2 / (BN * 4); int r_ = (s2 >> 2) % BN;\
                soff = 2 * ATB + t_ * BTB + sw64(r_ * 64 + q * 16);                 \
                g = (t_ == 0 ? gp2 : gp3) + (size_t)r_ * K + (k0_) + q * 8;         \
            }                                                                       \
            cp_async16(sb + (stage_) * STG + soff, g);                              \
        }                                                                           \
        asm volatile("cp.async.commit_group;");                                     \
    }

    GLOAD(0, 0);
    if (nch > 1) GLOAD(1, 32);

    const int arow = warp_m * (MT * 16) + (lane & 15);
    const int acolb = (lane >> 4) * 16;          // byte offset of 8-col group
    const int brow = warp_n * (NT * 8) + (lane & 7);
    const int bcolb = ((lane >> 3) & 1) * 16;

    for (int c = 0; c < nch; c++) {
        const int s = c % 3;
        if (c + 2 < nch) {
            GLOAD((c + 2) % 3, (c + 2) << 5);
            asm volatile("cp.async.wait_group 2;" ::: "memory");
        } else if (c + 1 < nch) {
            asm volatile("cp.async.wait_group 1;" ::: "memory");
        } else {
            asm volatile("cp.async.wait_group 0;" ::: "memory");
        }
        __syncthreads();

        uint32_t base = sb + s * STG;
#pragma unroll
        for (int ks = 0; ks < 2; ks++) {
            uint32_t a_hi[MT][4], a_lo[MT][4], b_hi[NT][2], b_lo[NT][2];
#pragma unroll
            for (int im = 0; im < MT; im++) {
                uint32_t off = sw64((arow + im * 16) * 64 + ks * 32 + acolb);
                ldm_x4(a_hi[im], base + 0 * ATB + off);
                ldm_x4(a_lo[im], base + 1 * ATB + off);
            }
#pragma unroll
            for (int jn = 0; jn < NT; jn++) {
                uint32_t off = sw64((brow + jn * 8) * 64 + ks * 32 + bcolb);
                ldm_x2(b_hi[jn], base + 2 * ATB + 0 * BTB + off);
                ldm_x2(b_lo[jn], base + 2 * ATB + 1 * BTB + off);
            }
#pragma unroll
            for (int im = 0; im < MT; im++)
#pragma unroll
                for (int jn = 0; jn < NT; jn++) {
                    mma_bf16(acc[im][jn], a_hi[im], b_hi[jn]);
                    mma_bf16(acc[im][jn], a_hi[im], b_lo[jn]);
                    mma_bf16(acc[im][jn], a_lo[im], b_hi[jn]);
                }
        }
        __syncthreads();
    }
#undef GLOAD

#pragma unroll
    for (int im = 0; im < MT; im++) {
        int r0 = bm + warp_m * (MT * 16) + im * 16 + (lane >> 2);
#pragma unroll
        for (int jn = 0; jn < NT; jn++) {
            int col = bn + warp_n * (NT * 8) + jn * 8 + (lane & 3) * 2;
            float2 v0; v0.x = acc[im][jn][0]; v0.y = acc[im][jn][1];
            float2 v1; v1.x = acc[im][jn][2]; v1.y = acc[im][jn][3];
            *(float2*)(C + (size_t)r0 * ldc + col) = v0;
            *(float2*)(C + (size_t)(r0 + 8) * ldc + col) = v1;
        }
    }
}

#define GSMEM128 (3 * (2 * 128 * 64 + 2 * 128 * 64))  // 98304
#define GSMEM64  (3 * (2 * 128 * 64 + 2 * 64 * 64))   // 73728

// ---------------- SIMT SGEMM (dt GEMM, K=32) -----------------------
template <int ACT>
__global__ void sgemm_kernel(const float* __restrict__ A, const float* __restrict__ W,
                             const float* __restrict__ bias, float* __restrict__ C,
                             int K, int lda, int ldw, int ldc) {
    __shared__ float As[16 * 132];
    __shared__ float Bs[16 * 68];
    const int tid = threadIdx.x;
    const int tx = tid & 15;
    const int ty = tid >> 4;
    const int bm = blockIdx.y * 128;
    const int bn = blockIdx.x * 64;

    const float* Ab = A + (size_t)bm * lda;
    const float* Wb = W + (size_t)bn * ldw;

    float acc[8][4];
#pragma unroll
    for (int i = 0; i < 8; i++)
#pragma unroll
        for (int j = 0; j < 4; j++) acc[i][j] = 0.f;

    for (int k0 = 0; k0 < K; k0 += 16) {
#pragma unroll
        for (int i = 0; i < 2; i++) {
            int qid = tid + i * 256;
            int r = qid >> 2, q = qid & 3;
            float4 v = *(const float4*)(Ab + (size_t)r * lda + k0 + q * 4);
            As[(q * 4 + 0) * 132 + r] = v.x;
            As[(q * 4 + 1) * 132 + r] = v.y;
            As[(q * 4 + 2) * 132 + r] = v.z;
            As[(q * 4 + 3) * 132 + r] = v.w;
        }
        {
            int r = tid >> 2, q = tid & 3;
            float4 v = *(const float4*)(Wb + (size_t)r * ldw + k0 + q * 4);
            Bs[(q * 4 + 0) * 68 + r] = v.x;
            Bs[(q * 4 + 1) * 68 + r] = v.y;
            Bs[(q * 4 + 2) * 68 + r] = v.z;
            Bs[(q * 4 + 3) * 68 + r] = v.w;
        }
        __syncthreads();
#pragma unroll
        for (int k = 0; k < 16; k++) {
            float4 a0 = *(const float4*)(As + k * 132 + ty * 8);
            float4 a1 = *(const float4*)(As + k * 132 + ty * 8 + 4);
            float4 b0 = *(const float4*)(Bs + k * 68 + tx * 4);
            float a[8] = {a0.x, a0.y, a0.z, a0.w, a1.x, a1.y, a1.z, a1.w};
            float bb[4] = {b0.x, b0.y, b0.z, b0.w};
#pragma unroll
            for (int i = 0; i < 8; i++)
#pragma unroll
                for (int j = 0; j < 4; j++) acc[i][j] = fmaf(a[i], bb[j], acc[i][j]);
        }
        __syncthreads();
    }

#pragma unroll
    for (int i = 0; i < 8; i++) {
        int row = bm + ty * 8 + i;
        int col = bn + tx * 4;
        float4 v;
        v.x = acc[i][0]; v.y = acc[i][1]; v.z = acc[i][2]; v.w = acc[i][3];
        if (ACT == 1) {
            v.x = softplusf(v.x + bias[col + 0]);
            v.y = softplusf(v.y + bias[col + 1]);
            v.z = softplusf(v.z + bias[col + 2]);
            v.w = softplusf(v.w + bias[col + 3]);
        }
        *(float4*)(C + (size_t)row * ldc + col) = v;
    }
}

// ------- depthwise causal conv + bias + SiLU; emits fp32 u AND bf16 hi/lo ----
__global__ void conv_silu_kernel(const float* __restrict__ xz, const float* __restrict__ w,
                                 const float* __restrict__ b, float* __restrict__ out,
                                 __nv_bfloat16* __restrict__ uhi, __nv_bfloat16* __restrict__ ulo) {
    int idx = blockIdx.x * 256 + threadIdx.x;
    if (idx >= ML * DI) return;
    int d = idx & (DI - 1);
    int bl = idx >> 10;
    int l = bl & (LL - 1);
    float acc = b[d];
#pragma unroll
    for (int k = 0; k < 4; k++) {
        int lk = l - 3 + k;
        if (lk >= 0) acc = fmaf(w[d * 4 + k], xz[(size_t)(bl - 3 + k) * (2 * DI) + d], acc);
    }
    float s = siluf(acc);
    out[idx] = s;
    __nv_bfloat16 hi = __float2bfloat16(s);
    uhi[idx] = hi;
    ulo[idx] = __float2bfloat16(s - __bfloat162float(hi));
}

// ------- selective scan, explicit software pipelining (unroll 8 + prefetch) --
// 64-thread blocks (4 channels) for even SM load balance.
#define SU 8
__global__ __launch_bounds__(64) void scan_kernel(
    const float* __restrict__ dtb, const float* __restrict__ ub,
    const float* __restrict__ xdbl, const float* __restrict__ A_log,
    float* __restrict__ ys) {
    int grp = threadIdx.x >> 4;
    int n = threadIdx.x & 15;
    int ch = blockIdx.x * 4 + grp;
    int b = ch >> 10;
    int d = ch & (DI - 1);

    float An2 = -__expf(A_log[d * DS + n]) * 1.4426950408889634f;

    const float* dtp = dtb + (size_t)b * LL * DI + d;
    const float* up  = ub  + (size_t)b * LL * DI + d;
    const float* bp  = xdbl + (size_t)b * LL * 64 + DTR + n;
    float* yp = ys + (size_t)b * LL * DI + d;

    float h = 0.f;
    float cdt[SU], cu[SU], cB[SU], cC[SU];
#pragma unroll
    for (int j = 0; j < SU; j++) {
        cdt[j] = __ldg(dtp + (size_t)j * DI);
        cu[j]  = __ldg(up + (size_t)j * DI);
        cB[j]  = __ldg(bp + (size_t)j * 64);
        cC[j]  = __ldg(bp + (size_t)j * 64 + DS);
    }
    for (int t0 = 0; t0 < LL; t0 += SU) {
        float ndt[SU], nu[SU], nB[SU], nC[SU];
        if (t0 + SU < LL) {
#pragma unroll
            for (int j = 0; j < SU; j++) {
                size_t o = (size_t)(t0 + SU + j);
                ndt[j] = __ldg(dtp + o * DI);
                nu[j]  = __ldg(up + o * DI);
                nB[j]  = __ldg(bp + o * 64);
                nC[j]  = __ldg(bp + o * 64 + DS);
            }
        }
#pragma unroll
        for (int j = 0; j < SU; j++) {
            float dA = ex2f(cdt[j] * An2);
            h = fmaf(dA, h, cdt[j] * cu[j] * cB[j]);
            float p = h * cC[j];
            p += __shfl_xor_sync(0xffffffffu, p, 8, 16);
            p += __shfl_xor_sync(0xffffffffu, p, 4, 16);
            p += __shfl_xor_sync(0xffffffffu, p, 2, 16);
            p += __shfl_xor_sync(0xffffffffu, p, 1, 16);
            if (n == 0) yp[(size_t)(t0 + j) * DI] = p;
        }
#pragma unroll
        for (int j = 0; j < SU; j++) {
            cdt[j] = ndt[j]; cu[j] = nu[j]; cB[j] = nB[j]; cC[j] = nC[j];
        }
    }
}

// ------- gate + bf16 split: y = (ys + u*D) * silu(z) -> hi/lo -----------------
__global__ void gate_split_kernel(const float* __restrict__ ys, const float* __restrict__ u,
                                  const float* __restrict__ xz, const float* __restrict__ Dskip,
                                  __nv_bfloat16* __restrict__ yhi, __nv_bfloat16* __restrict__ ylo) {
    int idx = blockIdx.x * 256 + threadIdx.x;
    if (idx >= ML * DI) return;
    int d = idx & (DI - 1);
    size_t bl = (size_t)(idx >> 10);
    float z = xz[bl * (2 * DI) + DI + d];
    float y = fmaf(u[idx], Dskip[d], ys[idx]) * siluf(z);
    __nv_bfloat16 hi = __float2bfloat16(y);
    yhi[idx] = hi;
    ylo[idx] = __float2bfloat16(y - __bfloat162float(hi));
}

// ---------------- LayerNorm ---------------------------------------
__global__ void ln_kernel(float* __restrict__ io, const float* __restrict__ w,
                          const float* __restrict__ b) {
    __shared__ float ssum[4], ssq[4];
    int row = blockIdx.x;
    float* p = io + (size_t)row * DM;
    int t = threadIdx.x;
    float4 v = ((float4*)p)[t];
    float s = v.x + v.y + v.z + v.w;
    float q = v.x * v.x + v.y * v.y + v.z * v.z + v.w * v.w;
#pragma unroll
    for (int o = 16; o; o >>= 1) {
        s += __shfl_xor_sync(0xffffffffu, s, o);
        q += __shfl_xor_sync(0xffffffffu, q, o);
    }
    if ((t & 31) == 0) { ssum[t >> 5] = s; ssq[t >> 5] = q; }
    __syncthreads();
    s = ssum[0] + ssum[1] + ssum[2] + ssum[3];
    q = ssq[0] + ssq[1] + ssq[2] + ssq[3];
    float mu = s * (1.f / DM);
    float var = q * (1.f / DM) - mu * mu;
    float inv = rsqrtf(var + 1e-5f);
    int c = t * 4;
    float4 o;
    o.x = (v.x - mu) * inv * w[c + 0] + b[c + 0];
    o.y = (v.y - mu) * inv * w[c + 1] + b[c + 1];
    o.z = (v.z - mu) * inv * w[c + 2] + b[c + 2];
    o.w = (v.w - mu) * inv * w[c + 3] + b[c + 3];
    ((float4*)p)[t] = o;
}

// ---------------- launch ------------------------------------------
extern "C" void kernel_launch(void* const* d_in, const int* in_sizes, int n_in,
                              void* d_out, int out_size) {
    const float* x_in      = (const float*)d_in[0];
    const float* in_proj_w = (const float*)d_in[1];
    const float* conv_w    = (const float*)d_in[2];
    const float* conv_b    = (const float*)d_in[3];
    const float* x_proj_w  = (const float*)d_in[4];
    const float* dt_proj_w = (const float*)d_in[5];
    const float* dt_proj_b = (const float*)d_in[6];
    const float* A_log     = (const float*)d_in[7];
    const float* D_skip    = (const float*)d_in[8];
    const float* out_proj_w= (const float*)d_in[9];
    const float* ln_w      = (const float*)d_in[10];
    const float* ln_b      = (const float*)d_in[11];
    float* out = (float*)d_out;

    static float *p_xz=nullptr,*p_xc=nullptr,*p_xdbl=nullptr,*p_dt=nullptr,*p_ys=nullptr;
    static __nv_bfloat16 *p_xhi,*p_xlo,*p_w1hi,*p_w1lo,*p_uhi,*p_ulo,*p_wxhi,*p_wxlo,
                         *p_yhi,*p_ylo,*p_w2hi,*p_w2lo;
    if (!p_xz) {
        cudaGetSymbolAddress((void**)&p_xz, g_xz);
        cudaGetSymbolAddress((void**)&p_xc, g_xc);
        cudaGetSymbolAddress((void**)&p_xdbl, g_xdbl);
        cudaGetSymbolAddress((void**)&p_dt, g_dt);
        cudaGetSymbolAddress((void**)&p_ys, g_ys);
        cudaGetSymbolAddress((void**)&p_xhi, g_xhi);
        cudaGetSymbolAddress((void**)&p_xlo, g_xlo);
        cudaGetSymbolAddress((void**)&p_w1hi, g_w1hi);
        cudaGetSymbolAddress((void**)&p_w1lo, g_w1lo);
        cudaGetSymbolAddress((void**)&p_uhi, g_uhi);
        cudaGetSymbolAddress((void**)&p_ulo, g_ulo);
        cudaGetSymbolAddress((void**)&p_wxhi, g_wxhi);
        cudaGetSymbolAddress((void**)&p_wxlo, g_wxlo);
        cudaGetSymbolAddress((void**)&p_yhi, g_yhi);
        cudaGetSymbolAddress((void**)&p_ylo, g_ylo);
        cudaGetSymbolAddress((void**)&p_w2hi, g_w2hi);
        cudaGetSymbolAddress((void**)&p_w2lo, g_w2lo);
        cudaFuncSetAttribute(mma_gemm_kernel<128>, cudaFuncAttributeMaxDynamicSharedMemorySize, GSMEM128);
        cudaFuncSetAttribute(mma_gemm_kernel<64>,  cudaFuncAttributeMaxDynamicSharedMemorySize, GSMEM64);
    }

    // 0) splits of inputs/weights
    cvt_split_kernel<<<(ML * DM / 4) / 256, 256>>>(x_in, p_xhi, p_xlo, ML * DM / 4);
    cvt_split_kernel<<<(2 * DI * DM / 4) / 256, 256>>>(in_proj_w, p_w1hi, p_w1lo, 2 * DI * DM / 4);
    cvt_split_kernel<<<(64 * DI / 4) / 256, 256>>>(x_proj_w, p_wxhi, p_wxlo, 64 * DI / 4);
    cvt_split_kernel<<<(DM * DI / 4) / 256, 256>>>(out_proj_w, p_w2hi, p_w2lo, DM * DI / 4);

    // 1) xz = X @ in_proj_w^T   [8192,2048]  (HMMA)
    mma_gemm_kernel<128><<<dim3(2 * DI / 128, ML / 128), 256, GSMEM128>>>(
        p_xhi, p_xlo, p_w1hi, p_w1lo, p_xz, DM, 2 * DI);

    // 2) u = silu(conv(x)+b)  (+ bf16 split of u)
    conv_silu_kernel<<<(ML * DI) / 256, 256>>>(p_xz, conv_w, conv_b, p_xc, p_uhi, p_ulo);

    // 3) x_dbl = u @ x_proj_w^T   [8192,64]  (HMMA, BN=64)
    mma_gemm_kernel<64><<<dim3(1, ML / 128), 256, GSMEM64>>>(
        p_uhi, p_ulo, p_wxhi, p_wxlo, p_xdbl, DI, 64);

    // 4) dt = softplus(x_dbl[:, :32] @ dt_proj_w^T + b)
    sgemm_kernel<1><<<dim3(DI / 64, ML / 128), 256>>>(p_xdbl, dt_proj_w, dt_proj_b, p_dt, DTR, 64, DTR, DI);

    // 5) selective scan (explicitly pipelined, 64-thread blocks)
    scan_kernel<<<BB * DI / 4, 64>>>(p_dt, p_xc, p_xdbl, A_log, p_ys);

    // 6) gate + bf16 split of y
    gate_split_kernel<<<(ML * DI) / 256, 256>>>(p_ys, p_xc, p_xz, D_skip, p_yhi, p_ylo);

    // 7) out = y @ out_proj_w^T  (HMMA)
    mma_gemm_kernel<128><<<dim3(DM / 128, ML / 128), 256, GSMEM128>>>(
        p_yhi, p_ylo, p_w2hi, p_w2lo, out, DI, DM);

    // 8) LayerNorm in place
    ln_kernel<<<ML, 128>>>(out, ln_w, ln_b);
}

// round 7
// speedup vs baseline: 6.0975x; 1.3678x over previous
#include <cuda_runtime.h>
#include <cuda_bf16.h>
#include <cuda_fp16.h>
#include <cstdint>
#include <cstddef>

// Problem constants
#define BB 4
#define LL 2048
#define DM 512
#define DI 1024            // D_INNER
#define DS 16              // D_STATE
#define DTR 32             // DT_RANK
#define ML (BB*LL)         // 8192 rows

// ---------------- scratch (no allocations allowed) ----------------
__device__ float g_xz  [(size_t)ML * 2 * DI];
__device__ float g_xc  [(size_t)ML * DI];
__device__ float g_xdbl[(size_t)ML * 64];
__device__ float g_dt  [(size_t)ML * DI];
__device__ float g_ys  [(size_t)ML * DI];

__device__ __align__(256) __half g_xh [(size_t)ML * DM];
__device__ __align__(256) __half g_w1h[(size_t)2 * DI * DM];
__device__ __align__(256) __half g_uh [(size_t)ML * DI];
__device__ __align__(256) __half g_wxh[(size_t)64 * DI];
__device__ __align__(256) __half g_yh [(size_t)ML * DI];
__device__ __align__(256) __half g_w2h[(size_t)DM * DI];

// ---------------- PTX helpers (base ISA only) ----------------
__device__ __forceinline__ uint32_t smem_u32(const void* p) {
    uint32_t a;
    asm("{ .reg .u64 t; cvta.to.shared.u64 t, %1; cvt.u32.u64 %0, t; }" : "=r"(a) : "l"(p));
    return a;
}
__device__ __forceinline__ void cp_async16(uint32_t saddr, const void* gaddr) {
    asm volatile("cp.async.cg.shared.global [%0], [%1], 16;" :: "r"(saddr), "l"(gaddr));
}
__device__ __forceinline__ void ldm_x4(uint32_t* r, uint32_t addr) {
    asm volatile("ldmatrix.sync.aligned.m8n8.x4.shared.b16 {%0,%1,%2,%3}, [%4];"
                 : "=r"(r[0]), "=r"(r[1]), "=r"(r[2]), "=r"(r[3]) : "r"(addr));
}
__device__ __forceinline__ void ldm_x2(uint32_t* r, uint32_t addr) {
    asm volatile("ldmatrix.sync.aligned.m8n8.x2.shared.b16 {%0,%1}, [%2];"
                 : "=r"(r[0]), "=r"(r[1]) : "r"(addr));
}
__device__ __forceinline__ void mma_f16(float* d, const uint32_t* a, const uint32_t* b) {
    asm volatile(
        "mma.sync.aligned.m16n8k16.row.col.f32.f16.f16.f32 "
        "{%0,%1,%2,%3}, {%4,%5,%6,%7}, {%8,%9}, {%0,%1,%2,%3};"
        : "+f"(d[0]), "+f"(d[1]), "+f"(d[2]), "+f"(d[3])
        : "r"(a[0]), "r"(a[1]), "r"(a[2]), "r"(a[3]), "r"(b[0]), "r"(b[1]));
}
__device__ __forceinline__ float ex2f(float x) {
    float y;
    asm("ex2.approx.f32 %0, %1;" : "=f"(y) : "f"(x));
    return y;
}
// XOR swizzle for 64B rows: conflict-free for 16B cp.async writes + ldmatrix
__device__ __forceinline__ uint32_t sw64(uint32_t o) { return o ^ ((o >> 3) & 0x30); }

// ---------------- math helpers ----------------
__device__ __forceinline__ float softplusf(float x) {
    return (x > 20.f) ? x : log1pf(__expf(x));
}
__device__ __forceinline__ float siluf(float x) {
    return x * __frcp_rn(1.f + __expf(-x));
}

// ---------------- fp32 -> fp16 convert -----------------------------
__global__ void cvt_half_kernel(const float* __restrict__ x, __half* __restrict__ h, int n4) {
    int i = blockIdx.x * 256 + threadIdx.x;
    if (i >= n4) return;
    float4 v = ((const float4*)x)[i];
    __half2 h0 = __floats2half2_rn(v.x, v.y);
    __half2 h1 = __floats2half2_rn(v.z, v.w);
    ((__half2*)h)[i * 2 + 0] = h0;
    ((__half2*)h)[i * 2 + 1] = h1;
}

// ---------------- HMMA fp16 GEMM -----------------------------------
// C[m,n] = sum_k A[m,k]*W[n,k]; fp16 operands, fp32 accumulate.
// 64B rows (BK=32 halves), XOR-swizzled, 3-stage cp.async pipeline.
template <int BN>
__global__ __launch_bounds__(256) void mma_gemm_kernel(
    const __half* __restrict__ A, const __half* __restrict__ B,
    float* __restrict__ C, int K, int ldc) {
    constexpr int NWN = (BN == 128) ? 4 : 2;   // warps along N
    constexpr int NWM = 8 / NWN;               // warps along M
    constexpr int MT = (128 / NWM) / 16;       // 16-row m-tiles per warp
    constexpr int NT = (BN / NWN) / 8;         // 8-col n-tiles per warp
    constexpr int ATB = 128 * 64;              // A tile bytes
    constexpr int BTB = BN * 64;               // B tile bytes
    constexpr int STG = ATB + BTB;             // bytes per stage
    constexpr int NSEG = (128 + BN) * 4;       // 16B segments per stage

    extern __shared__ __align__(128) char smem[];
    const int tid = threadIdx.x;
    const int lane = tid & 31;
    const int wid = tid >> 5;
    const int warp_m = wid / NWN;
    const int warp_n = wid % NWN;
    const int bm = blockIdx.y * 128;
    const int bn = blockIdx.x * BN;

    uint32_t sb = smem_u32(smem);
    const __half* gpa = A + (size_t)bm * K;
    const __half* gpb = B + (size_t)bn * K;

    float acc[MT][NT][4];
#pragma unroll
    for (int i = 0; i < MT; i++)
#pragma unroll
        for (int j = 0; j < NT; j++)
#pragma unroll
            for (int v = 0; v < 4; v++) acc[i][j][v] = 0.f;

    const int nch = K >> 5;

#define GLOAD(stage_, k0_)                                                          \
    {                                                                               \
        _Pragma("unroll")                                                           \
        for (int i = 0; i < NSEG / 256; i++) {                                      \
            int seg = tid + i * 256;                                                \
            int q = seg & 3;                                                        \
            uint32_t soff; const __half* g;                                         \
            if (seg < 512) {                                                        \
                int r_ = seg >> 2;                                                  \
                soff = sw64(r_ * 64 + q * 16);                                      \
                g = gpa + (size_t)r_ * K + (k0_) + q * 8;                           \
            } else {                                                                \
                int r_ = (seg - 512) >> 2;                                          \
                soff = ATB + sw64(r_ * 64 + q * 16);                                \
                g = gpb + (size_t)r_ * K + (k0_) + q * 8;                           \
            }                                                                       \
            cp_async16(sb + (stage_) * STG + soff, g);                              \
        }                                                                           \
        asm volatile("cp.async.commit_group;");                                     \
    }

    GLOAD(0, 0);
    if (nch > 1) GLOAD(1, 32);

    const int arow = warp_m * (MT * 16) + (lane & 15);
    const int acolb = (lane >> 4) * 16;          // byte offset of 8-col group
    const int brow = warp_n * (NT * 8) + (lane & 7);
    const int bcolb = ((lane >> 3) & 1) * 16;

    for (int c = 0; c < nch; c++) {
        const int s = c % 3;
        if (c + 2 < nch) {
            GLOAD((c + 2) % 3, (c + 2) << 5);
            asm volatile("cp.async.wait_group 2;" ::: "memory");
        } else if (c + 1 < nch) {
            asm volatile("cp.async.wait_group 1;" ::: "memory");
        } else {
            asm volatile("cp.async.wait_group 0;" ::: "memory");
        }
        __syncthreads();

        uint32_t base = sb + s * STG;
#pragma unroll
        for (int ks = 0; ks < 2; ks++) {
            uint32_t a_f[MT][4], b_f[NT][2];
#pragma unroll
            for (int im = 0; im < MT; im++) {
                uint32_t off = sw64((arow + im * 16) * 64 + ks * 32 + acolb);
                ldm_x4(a_f[im], base + off);
            }
#pragma unroll
            for (int jn = 0; jn < NT; jn++) {
                uint32_t off = sw64((brow + jn * 8) * 64 + ks * 32 + bcolb);
                ldm_x2(b_f[jn], base + ATB + off);
            }
#pragma unroll
            for (int im = 0; im < MT; im++)
#pragma unroll
                for (int jn = 0; jn < NT; jn++)
                    mma_f16(acc[im][jn], a_f[im], b_f[jn]);
        }
        __syncthreads();
    }
#undef GLOAD

#pragma unroll
    for (int im = 0; im < MT; im++) {
        int r0 = bm + warp_m * (MT * 16) + im * 16 + (lane >> 2);
#pragma unroll
        for (int jn = 0; jn < NT; jn++) {
            int col = bn + warp_n * (NT * 8) + jn * 8 + (lane & 3) * 2;
            float2 v0; v0.x = acc[im][jn][0]; v0.y = acc[im][jn][1];
            float2 v1; v1.x = acc[im][jn][2]; v1.y = acc[im][jn][3];
            *(float2*)(C + (size_t)r0 * ldc + col) = v0;
            *(float2*)(C + (size_t)(r0 + 8) * ldc + col) = v1;
        }
    }
}

#define GSMEM128 (3 * (128 * 64 + 128 * 64))  // 49152
#define GSMEM64  (3 * (128 * 64 + 64 * 64))   // 36864

// ---------------- SIMT SGEMM (dt GEMM, K=32) -----------------------
template <int ACT>
__global__ void sgemm_kernel(const float* __restrict__ A, const float* __restrict__ W,
                             const float* __restrict__ bias, float* __restrict__ C,
                             int K, int lda, int ldw, int ldc) {
    __shared__ float As[16 * 132];
    __shared__ float Bs[16 * 68];
    const int tid = threadIdx.x;
    const int tx = tid & 15;
    const int ty = tid >> 4;
    const int bm = blockIdx.y * 128;
    const int bn = blockIdx.x * 64;

    const float* Ab = A + (size_t)bm * lda;
    const float* Wb = W + (size_t)bn * ldw;

    float acc[8][4];
#pragma unroll
    for (int i = 0; i < 8; i++)
#pragma unroll
        for (int j = 0; j < 4; j++) acc[i][j] = 0.f;

    for (int k0 = 0; k0 < K; k0 += 16) {
#pragma unroll
        for (int i = 0; i < 2; i++) {
            int qid = tid + i * 256;
            int r = qid >> 2, q = qid & 3;
            float4 v = *(const float4*)(Ab + (size_t)r * lda + k0 + q * 4);
            As[(q * 4 + 0) * 132 + r] = v.x;
            As[(q * 4 + 1) * 132 + r] = v.y;
            As[(q * 4 + 2) * 132 + r] = v.z;
            As[(q * 4 + 3) * 132 + r] = v.w;
        }
        {
            int r = tid >> 2, q = tid & 3;
            float4 v = *(const float4*)(Wb + (size_t)r * ldw + k0 + q * 4);
            Bs[(q * 4 + 0) * 68 + r] = v.x;
            Bs[(q * 4 + 1) * 68 + r] = v.y;
            Bs[(q * 4 + 2) * 68 + r] = v.z;
            Bs[(q * 4 + 3) * 68 + r] = v.w;
        }
        __syncthreads();
#pragma unroll
        for (int k = 0; k < 16; k++) {
            float4 a0 = *(const float4*)(As + k * 132 + ty * 8);
            float4 a1 = *(const float4*)(As + k * 132 + ty * 8 + 4);
            float4 b0 = *(const float4*)(Bs + k * 68 + tx * 4);
            float a[8] = {a0.x, a0.y, a0.z, a0.w, a1.x, a1.y, a1.z, a1.w};
            float bb[4] = {b0.x, b0.y, b0.z, b0.w};
#pragma unroll
            for (int i = 0; i < 8; i++)
#pragma unroll
                for (int j = 0; j < 4; j++) acc[i][j] = fmaf(a[i], bb[j], acc[i][j]);
        }
        __syncthreads();
    }

#pragma unroll
    for (int i = 0; i < 8; i++) {
        int row = bm + ty * 8 + i;
        int col = bn + tx * 4;
        float4 v;
        v.x = acc[i][0]; v.y = acc[i][1]; v.z = acc[i][2]; v.w = acc[i][3];
        if (ACT == 1) {
            v.x = softplusf(v.x + bias[col + 0]);
            v.y = softplusf(v.y + bias[col + 1]);
            v.z = softplusf(v.z + bias[col + 2]);
            v.w = softplusf(v.w + bias[col + 3]);
        }
        *(float4*)(C + (size_t)row * ldc + col) = v;
    }
}

// ------- depthwise causal conv + bias + SiLU; emits fp32 u AND fp16 u --------
__global__ void conv_silu_kernel(const float* __restrict__ xz, const float* __restrict__ w,
                                 const float* __restrict__ b, float* __restrict__ out,
                                 __half* __restrict__ uh) {
    int idx = blockIdx.x * 256 + threadIdx.x;
    if (idx >= ML * DI) return;
    int d = idx & (DI - 1);
    int bl = idx >> 10;
    int l = bl & (LL - 1);
    float acc = b[d];
#pragma unroll
    for (int k = 0; k < 4; k++) {
        int lk = l - 3 + k;
        if (lk >= 0) acc = fmaf(w[d * 4 + k], xz[(size_t)(bl - 3 + k) * (2 * DI) + d], acc);
    }
    float s = siluf(acc);
    out[idx] = s;
    uh[idx] = __float2half_rn(s);
}

// ------- selective scan, explicit software pipelining (unroll 8 + prefetch) --
#define SU 8
__global__ __launch_bounds__(64) void scan_kernel(
    const float* __restrict__ dtb, const float* __restrict__ ub,
    const float* __restrict__ xdbl, const float* __restrict__ A_log,
    float* __restrict__ ys) {
    int grp = threadIdx.x >> 4;
    int n = threadIdx.x & 15;
    int ch = blockIdx.x * 4 + grp;
    int b = ch >> 10;
    int d = ch & (DI - 1);

    float An2 = -__expf(A_log[d * DS + n]) * 1.4426950408889634f;

    const float* dtp = dtb + (size_t)b * LL * DI + d;
    const float* up  = ub  + (size_t)b * LL * DI + d;
    const float* bp  = xdbl + (size_t)b * LL * 64 + DTR + n;
    float* yp = ys + (size_t)b * LL * DI + d;

    float h = 0.f;
    float cdt[SU], cu[SU], cB[SU], cC[SU];
#pragma unroll
    for (int j = 0; j < SU; j++) {
        cdt[j] = __ldg(dtp + (size_t)j * DI);
        cu[j]  = __ldg(up + (size_t)j * DI);
        cB[j]  = __ldg(bp + (size_t)j * 64);
        cC[j]  = __ldg(bp + (size_t)j * 64 + DS);
    }
    for (int t0 = 0; t0 < LL; t0 += SU) {
        float ndt[SU], nu[SU], nB[SU], nC[SU];
        if (t0 + SU < LL) {
#pragma unroll
            for (int j = 0; j < SU; j++) {
                size_t o = (size_t)(t0 + SU + j);
                ndt[j] = __ldg(dtp + o * DI);
                nu[j]  = __ldg(up + o * DI);
                nB[j]  = __ldg(bp + o * 64);
                nC[j]  = __ldg(bp + o * 64 + DS);
            }
        }
#pragma unroll
        for (int j = 0; j < SU; j++) {
            float dA = ex2f(cdt[j] * An2);
            h = fmaf(dA, h, cdt[j] * cu[j] * cB[j]);
            float p = h * cC[j];
            p += __shfl_xor_sync(0xffffffffu, p, 8, 16);
            p += __shfl_xor_sync(0xffffffffu, p, 4, 16);
            p += __shfl_xor_sync(0xffffffffu, p, 2, 16);
            p += __shfl_xor_sync(0xffffffffu, p, 1, 16);
            if (n == 0) yp[(size_t)(t0 + j) * DI] = p;
        }
#pragma unroll
        for (int j = 0; j < SU; j++) {
            cdt[j] = ndt[j]; cu[j] = nu[j]; cB[j] = nB[j]; cC[j] = nC[j];
        }
    }
}

// ------- gate: y = (ys + u*D) * silu(z) -> fp16 ------------------------------
__global__ void gate_kernel(const float* __restrict__ ys, const float* __restrict__ u,
                            const float* __restrict__ xz, const float* __restrict__ Dskip,
                            __half* __restrict__ yh) {
    int idx = blockIdx.x * 256 + threadIdx.x;
    if (idx >= ML * DI) return;
    int d = idx & (DI - 1);
    size_t bl = (size_t)(idx >> 10);
    float z = xz[bl * (2 * DI) + DI + d];
    float y = fmaf(u[idx], Dskip[d], ys[idx]) * siluf(z);
    yh[idx] = __float2half_rn(y);
}

// ---------------- LayerNorm ---------------------------------------
__global__ void ln_kernel(float* __restrict__ io, const float* __restrict__ w,
                          const float* __restrict__ b) {
    __shared__ float ssum[4], ssq[4];
    int row = blockIdx.x;
    float* p = io + (size_t)row * DM;
    int t = threadIdx.x;
    float4 v = ((float4*)p)[t];
    float s = v.x + v.y + v.z + v.w;
    float q = v.x * v.x + v.y * v.y + v.z * v.z + v.w * v.w;
#pragma unroll
    for (int o = 16; o; o >>= 1) {
        s += __shfl_xor_sync(0xffffffffu, s, o);
        q += __shfl_xor_sync(0xffffffffu, q, o);
    }
    if ((t & 31) == 0) { ssum[t >> 5] = s; ssq[t >> 5] = q; }
    __syncthreads();
    s = ssum[0] + ssum[1] + ssum[2] + ssum[3];
    q = ssq[0] + ssq[1] + ssq[2] + ssq[3];
    float mu = s * (1.f / DM);
    float var = q * (1.f / DM) - mu * mu;
    float inv = rsqrtf(var + 1e-5f);
    int c = t * 4;
    float4 o;
    o.x = (v.x - mu) * inv * w[c + 0] + b[c + 0];
    o.y = (v.y - mu) * inv * w[c + 1] + b[c + 1];
    o.z = (v.z - mu) * inv * w[c + 2] + b[c + 2];
    o.w = (v.w - mu) * inv * w[c + 3] + b[c + 3];
    ((float4*)p)[t] = o;
}

// ---------------- launch ------------------------------------------
extern "C" void kernel_launch(void* const* d_in, const int* in_sizes, int n_in,
                              void* d_out, int out_size) {
    const float* x_in      = (const float*)d_in[0];
    const float* in_proj_w = (const float*)d_in[1];
    const float* conv_w    = (const float*)d_in[2];
    const float* conv_b    = (const float*)d_in[3];
    const float* x_proj_w  = (const float*)d_in[4];
    const float* dt_proj_w = (const float*)d_in[5];
    const float* dt_proj_b = (const float*)d_in[6];
    const float* A_log     = (const float*)d_in[7];
    const float* D_skip    = (const float*)d_in[8];
    const float* out_proj_w= (const float*)d_in[9];
    const float* ln_w      = (const float*)d_in[10];
    const float* ln_b      = (const float*)d_in[11];
    float* out = (float*)d_out;

    static float *p_xz=nullptr,*p_xc=nullptr,*p_xdbl=nullptr,*p_dt=nullptr,*p_ys=nullptr;
    static __half *p_xh,*p_w1h,*p_uh,*p_wxh,*p_yh,*p_w2h;
    if (!p_xz) {
        cudaGetSymbolAddress((void**)&p_xz, g_xz);
        cudaGetSymbolAddress((void**)&p_xc, g_xc);
        cudaGetSymbolAddress((void**)&p_xdbl, g_xdbl);
        cudaGetSymbolAddress((void**)&p_dt, g_dt);
        cudaGetSymbolAddress((void**)&p_ys, g_ys);
        cudaGetSymbolAddress((void**)&p_xh, g_xh);
        cudaGetSymbolAddress((void**)&p_w1h, g_w1h);
        cudaGetSymbolAddress((void**)&p_uh, g_uh);
        cudaGetSymbolAddress((void**)&p_wxh, g_wxh);
        cudaGetSymbolAddress((void**)&p_yh, g_yh);
        cudaGetSymbolAddress((void**)&p_w2h, g_w2h);
        cudaFuncSetAttribute(mma_gemm_kernel<128>, cudaFuncAttributeMaxDynamicSharedMemorySize, GSMEM128);
        cudaFuncSetAttribute(mma_gemm_kernel<64>,  cudaFuncAttributeMaxDynamicSharedMemorySize, GSMEM64);
    }

    // 0) fp16 converts of inputs/weights
    cvt_half_kernel<<<(ML * DM / 4) / 256, 256>>>(x_in, p_xh, ML * DM / 4);
    cvt_half_kernel<<<(2 * DI * DM / 4) / 256, 256>>>(in_proj_w, p_w1h, 2 * DI * DM / 4);
    cvt_half_kernel<<<(64 * DI / 4) / 256, 256>>>(x_proj_w, p_wxh, 64 * DI / 4);
    cvt_half_kernel<<<(DM * DI / 4) / 256, 256>>>(out_proj_w, p_w2h, DM * DI / 4);

    // 1) xz = X @ in_proj_w^T   [8192,2048]  (fp16 HMMA)
    mma_gemm_kernel<128><<<dim3(2 * DI / 128, ML / 128), 256, GSMEM128>>>(
        p_xh, p_w1h, p_xz, DM, 2 * DI);

    // 2) u = silu(conv(x)+b)  (+ fp16 u)
    conv_silu_kernel<<<(ML * DI) / 256, 256>>>(p_xz, conv_w, conv_b, p_xc, p_uh);

    // 3) x_dbl = u @ x_proj_w^T   [8192,64]  (fp16 HMMA, BN=64)
    mma_gemm_kernel<64><<<dim3(1, ML / 128), 256, GSMEM64>>>(
        p_uh, p_wxh, p_xdbl, DI, 64);

    // 4) dt = softplus(x_dbl[:, :32] @ dt_proj_w^T + b)
    sgemm_kernel<1><<<dim3(DI / 64, ML / 128), 256>>>(p_xdbl, dt_proj_w, dt_proj_b, p_dt, DTR, 64, DTR, DI);

    // 5) selective scan (explicitly pipelined, 64-thread blocks)
    scan_kernel<<<BB * DI / 4, 64>>>(p_dt, p_xc, p_xdbl, A_log, p_ys);

    // 6) gate -> fp16 y
    gate_kernel<<<(ML * DI) / 256, 256>>>(p_ys, p_xc, p_xz, D_skip, p_yh);

    // 7) out = y @ out_proj_w^T  (fp16 HMMA)
    mma_gemm_kernel<128><<<dim3(DM / 128, ML / 128), 256, GSMEM128>>>(
        p_yh, p_w2h, out, DI, DM);

    // 8) LayerNorm in place
    ln_kernel<<<ML, 128>>>(out, ln_w, ln_b);
}

// round 8
// speedup vs baseline: 6.4708x; 1.0612x over previous
#include <cuda_runtime.h>
#include <cuda_bf16.h>
#include <cuda_fp16.h>
#include <cstdint>
#include <cstddef>

// Problem constants
#define BB 4
#define LL 2048
#define DM 512
#define DI 1024            // D_INNER
#define DS 16              // D_STATE
#define DTR 32             // DT_RANK
#define ML (BB*LL)         // 8192 rows

// ---------------- scratch (no allocations allowed) ----------------
__device__ float g_xz  [(size_t)ML * 2 * DI];
__device__ float g_xc  [(size_t)ML * DI];
__device__ float g_xdbl[(size_t)ML * 64];       // cols: 0..31 dt_lr, 32+2n = B_n, 33+2n = C_n
__device__ float g_dtdu[(size_t)ML * DI * 2];   // interleaved (dt, dt*u)
__device__ float g_ys  [(size_t)ML * DI];

__device__ __align__(256) __half g_xh [(size_t)ML * DM];
__device__ __align__(256) __half g_w1h[(size_t)2 * DI * DM];
__device__ __align__(256) __half g_uh [(size_t)ML * DI];
__device__ __align__(256) __half g_wxh[(size_t)64 * DI];
__device__ __align__(256) __half g_yh [(size_t)ML * DI];
__device__ __align__(256) __half g_w2h[(size_t)DM * DI];

// ---------------- PTX helpers (base ISA only) ----------------
__device__ __forceinline__ uint32_t smem_u32(const void* p) {
    uint32_t a;
    asm("{ .reg .u64 t; cvta.to.shared.u64 t, %1; cvt.u32.u64 %0, t; }" : "=r"(a) : "l"(p));
    return a;
}
__device__ __forceinline__ void cp_async16(uint32_t saddr, const void* gaddr) {
    asm volatile("cp.async.cg.shared.global [%0], [%1], 16;" :: "r"(saddr), "l"(gaddr));
}
__device__ __forceinline__ void ldm_x4(uint32_t* r, uint32_t addr) {
    asm volatile("ldmatrix.sync.aligned.m8n8.x4.shared.b16 {%0,%1,%2,%3}, [%4];"
                 : "=r"(r[0]), "=r"(r[1]), "=r"(r[2]), "=r"(r[3]) : "r"(addr));
}
__device__ __forceinline__ void ldm_x2(uint32_t* r, uint32_t addr) {
    asm volatile("ldmatrix.sync.aligned.m8n8.x2.shared.b16 {%0,%1}, [%2];"
                 : "=r"(r[0]), "=r"(r[1]) : "r"(addr));
}
__device__ __forceinline__ void mma_f16(float* d, const uint32_t* a, const uint32_t* b) {
    asm volatile(
        "mma.sync.aligned.m16n8k16.row.col.f32.f16.f16.f32 "
        "{%0,%1,%2,%3}, {%4,%5,%6,%7}, {%8,%9}, {%0,%1,%2,%3};"
        : "+f"(d[0]), "+f"(d[1]), "+f"(d[2]), "+f"(d[3])
        : "r"(a[0]), "r"(a[1]), "r"(a[2]), "r"(a[3]), "r"(b[0]), "r"(b[1]));
}
__device__ __forceinline__ float ex2f(float x) {
    float y;
    asm("ex2.approx.f32 %0, %1;" : "=f"(y) : "f"(x));
    return y;
}
// XOR swizzle for 64B rows: conflict-free for 16B cp.async writes + ldmatrix
__device__ __forceinline__ uint32_t sw64(uint32_t o) { return o ^ ((o >> 3) & 0x30); }

// ---------------- math helpers ----------------
__device__ __forceinline__ float softplusf(float x) {
    return (x > 20.f) ? x : log1pf(__expf(x));
}
__device__ __forceinline__ float siluf(float x) {
    return x * __frcp_rn(1.f + __expf(-x));
}

// ---------------- fp32 -> fp16 convert -----------------------------
__global__ void cvt_half_kernel(const float* __restrict__ x, __half* __restrict__ h, int n4) {
    int i = blockIdx.x * 256 + threadIdx.x;
    if (i >= n4) return;
    float4 v = ((const float4*)x)[i];
    __half2 h0 = __floats2half2_rn(v.x, v.y);
    __half2 h1 = __floats2half2_rn(v.z, v.w);
    ((__half2*)h)[i * 2 + 0] = h0;
    ((__half2*)h)[i * 2 + 1] = h1;
}

// ------- fp32 -> fp16 convert with B/C row interleave for x_proj_w ----------
// src row j -> dst row: j<32 -> j ; 32<=j<48 -> 32+2(j-32) ; 48<=j<64 -> 33+2(j-48)
__global__ void cvt_half_wx_kernel(const float* __restrict__ x, __half* __restrict__ h) {
    int i = blockIdx.x * 256 + threadIdx.x;       // over 64*DI/4 float4s
    if (i >= 64 * DI / 4) return;
    int row = i / (DI / 4);
    int off = i % (DI / 4);
    int dst = (row < 32) ? row : ((row < 48) ? 32 + 2 * (row - 32) : 33 + 2 * (row - 48));
    float4 v = ((const float4*)x)[i];
    __half2 h0 = __floats2half2_rn(v.x, v.y);
    __half2 h1 = __floats2half2_rn(v.z, v.w);
    ((__half2*)(h + (size_t)dst * DI))[off * 2 + 0] = h0;
    ((__half2*)(h + (size_t)dst * DI))[off * 2 + 1] = h1;
}

// ---------------- HMMA fp16 GEMM -----------------------------------
template <int BN>
__global__ __launch_bounds__(256) void mma_gemm_kernel(
    const __half* __restrict__ A, const __half* __restrict__ B,
    float* __restrict__ C, int K, int ldc) {
    constexpr int NWN = (BN == 128) ? 4 : 2;
    constexpr int NWM = 8 / NWN;
    constexpr int MT = (128 / NWM) / 16;
    constexpr int NT = (BN / NWN) / 8;
    constexpr int ATB = 128 * 64;
    constexpr int BTB = BN * 64;
    constexpr int STG = ATB + BTB;
    constexpr int NSEG = (128 + BN) * 4;

    extern __shared__ __align__(128) char smem[];
    const int tid = threadIdx.x;
    const int lane = tid & 31;
    const int wid = tid >> 5;
    const int warp_m = wid / NWN;
    const int warp_n = wid % NWN;
    const int bm = blockIdx.y * 128;
    const int bn = blockIdx.x * BN;

    uint32_t sb = smem_u32(smem);
    const __half* gpa = A + (size_t)bm * K;
    const __half* gpb = B + (size_t)bn * K;

    float acc[MT][NT][4];
#pragma unroll
    for (int i = 0; i < MT; i++)
#pragma unroll
        for (int j = 0; j < NT; j++)
#pragma unroll
            for (int v = 0; v < 4; v++) acc[i][j][v] = 0.f;

    const int nch = K >> 5;

#define GLOAD(stage_, k0_)                                                          \
    {                                                                               \
        _Pragma("unroll")                                                           \
        for (int i = 0; i < NSEG / 256; i++) {                                      \
            int seg = tid + i * 256;                                                \
            int q = seg & 3;                                                        \
            uint32_t soff; const __half* g;                                         \
            if (seg < 512) {                                                        \
                int r_ = seg >> 2;                                                  \
                soff = sw64(r_ * 64 + q * 16);                                      \
                g = gpa + (size_t)r_ * K + (k0_) + q * 8;                           \
            } else {                                                                \
                int r_ = (seg - 512) >> 2;                                          \
                soff = ATB + sw64(r_ * 64 + q * 16);                                \
                g = gpb + (size_t)r_ * K + (k0_) + q * 8;                           \
            }                                                                       \
            cp_async16(sb + (stage_) * STG + soff, g);                              \
        }                                                                           \
        asm volatile("cp.async.commit_group;");                                     \
    }

    GLOAD(0, 0);
    if (nch > 1) GLOAD(1, 32);

    const int arow = warp_m * (MT * 16) + (lane & 15);
    const int acolb = (lane >> 4) * 16;
    const int brow = warp_n * (NT * 8) + (lane & 7);
    const int bcolb = ((lane >> 3) & 1) * 16;

    for (int c = 0; c < nch; c++) {
        const int s = c % 3;
        if (c + 2 < nch) {
            GLOAD((c + 2) % 3, (c + 2) << 5);
            asm volatile("cp.async.wait_group 2;" ::: "memory");
        } else if (c + 1 < nch) {
            asm volatile("cp.async.wait_group 1;" ::: "memory");
        } else {
            asm volatile("cp.async.wait_group 0;" ::: "memory");
        }
        __syncthreads();

        uint32_t base = sb + s * STG;
#pragma unroll
        for (int ks = 0; ks < 2; ks++) {
            uint32_t a_f[MT][4], b_f[NT][2];
#pragma unroll
            for (int im = 0; im < MT; im++) {
                uint32_t off = sw64((arow + im * 16) * 64 + ks * 32 + acolb);
                ldm_x4(a_f[im], base + off);
            }
#pragma unroll
            for (int jn = 0; jn < NT; jn++) {
                uint32_t off = sw64((brow + jn * 8) * 64 + ks * 32 + bcolb);
                ldm_x2(b_f[jn], base + ATB + off);
            }
#pragma unroll
            for (int im = 0; im < MT; im++)
#pragma unroll
                for (int jn = 0; jn < NT; jn++)
                    mma_f16(acc[im][jn], a_f[im], b_f[jn]);
        }
        __syncthreads();
    }
#undef GLOAD

#pragma unroll
    for (int im = 0; im < MT; im++) {
        int r0 = bm + warp_m * (MT * 16) + im * 16 + (lane >> 2);
#pragma unroll
        for (int jn = 0; jn < NT; jn++) {
            int col = bn + warp_n * (NT * 8) + jn * 8 + (lane & 3) * 2;
            float2 v0; v0.x = acc[im][jn][0]; v0.y = acc[im][jn][1];
            float2 v1; v1.x = acc[im][jn][2]; v1.y = acc[im][jn][3];
            *(float2*)(C + (size_t)r0 * ldc + col) = v0;
            *(float2*)(C + (size_t)(r0 + 8) * ldc + col) = v1;
        }
    }
}

#define GSMEM128 (3 * (128 * 64 + 128 * 64))  // 49152
#define GSMEM64  (3 * (128 * 64 + 64 * 64))   // 36864

// ----- dt SGEMM (K=32): dt = softplus(x_dbl[:,0:32] @ dt_proj_w^T + b)
// writes interleaved (dt, dt*u) float2 pairs into dtdu
__global__ void sgemm_dt_kernel(const float* __restrict__ A, const float* __restrict__ W,
                                const float* __restrict__ bias, const float* __restrict__ u,
                                float* __restrict__ dtdu) {
    __shared__ float As[16 * 132];
    __shared__ float Bs[16 * 68];
    const int tid = threadIdx.x;
    const int tx = tid & 15;
    const int ty = tid >> 4;
    const int bm = blockIdx.y * 128;
    const int bn = blockIdx.x * 64;

    const float* Ab = A + (size_t)bm * 64;
    const float* Wb = W + (size_t)bn * DTR;

    float acc[8][4];
#pragma unroll
    for (int i = 0; i < 8; i++)
#pragma unroll
        for (int j = 0; j < 4; j++) acc[i][j] = 0.f;

    for (int k0 = 0; k0 < DTR; k0 += 16) {
#pragma unroll
        for (int i = 0; i < 2; i++) {
            int qid = tid + i * 256;
            int r = qid >> 2, q = qid & 3;
            float4 v = *(const float4*)(Ab + (size_t)r * 64 + k0 + q * 4);
            As[(q * 4 + 0) * 132 + r] = v.x;
            As[(q * 4 + 1) * 132 + r] = v.y;
            As[(q * 4 + 2) * 132 + r] = v.z;
            As[(q * 4 + 3) * 132 + r] = v.w;
        }
        {
            int r = tid >> 2, q = tid & 3;
            float4 v = *(const float4*)(Wb + (size_t)r * DTR + k0 + q * 4);
            Bs[(q * 4 + 0) * 68 + r] = v.x;
            Bs[(q * 4 + 1) * 68 + r] = v.y;
            Bs[(q * 4 + 2) * 68 + r] = v.z;
            Bs[(q * 4 + 3) * 68 + r] = v.w;
        }
        __syncthreads();
#pragma unroll
        for (int k = 0; k < 16; k++) {
            float4 a0 = *(const float4*)(As + k * 132 + ty * 8);
            float4 a1 = *(const float4*)(As + k * 132 + ty * 8 + 4);
            float4 b0 = *(const float4*)(Bs + k * 68 + tx * 4);
            float a[8] = {a0.x, a0.y, a0.z, a0.w, a1.x, a1.y, a1.z, a1.w};
            float bb[4] = {b0.x, b0.y, b0.z, b0.w};
#pragma unroll
            for (int i = 0; i < 8; i++)
#pragma unroll
                for (int j = 0; j < 4; j++) acc[i][j] = fmaf(a[i], bb[j], acc[i][j]);
        }
        __syncthreads();
    }

#pragma unroll
    for (int i = 0; i < 8; i++) {
        int row = bm + ty * 8 + i;
        int col = bn + tx * 4;
        float4 uv = *(const float4*)(u + (size_t)row * DI + col);
        float d0 = softplusf(acc[i][0] + bias[col + 0]);
        float d1 = softplusf(acc[i][1] + bias[col + 1]);
        float d2 = softplusf(acc[i][2] + bias[col + 2]);
        float d3 = softplusf(acc[i][3] + bias[col + 3]);
        float4 o0; o0.x = d0; o0.y = d0 * uv.x; o0.z = d1; o0.w = d1 * uv.y;
        float4 o1; o1.x = d2; o1.y = d2 * uv.z; o1.z = d3; o1.w = d3 * uv.w;
        float* dst = dtdu + (size_t)row * (2 * DI) + 2 * col;
        *(float4*)(dst + 0) = o0;
        *(float4*)(dst + 4) = o1;
    }
}

// ------- depthwise causal conv + bias + SiLU; emits fp32 u AND fp16 u --------
__global__ void conv_silu_kernel(const float* __restrict__ xz, const float* __restrict__ w,
                                 const float* __restrict__ b, float* __restrict__ out,
                                 __half* __restrict__ uh) {
    int idx = blockIdx.x * 256 + threadIdx.x;
    if (idx >= ML * DI) return;
    int d = idx & (DI - 1);
    int bl = idx >> 10;
    int l = bl & (LL - 1);
    float acc = b[d];
#pragma unroll
    for (int k = 0; k < 4; k++) {
        int lk = l - 3 + k;
        if (lk >= 0) acc = fmaf(w[d * 4 + k], xz[(size_t)(bl - 3 + k) * (2 * DI) + d], acc);
    }
    float s = siluf(acc);
    out[idx] = s;
    uh[idx] = __float2half_rn(s);
}

// ------- selective scan: packed float2 loads, SW-pipelined (unroll 8) --------
#define SU 8
__global__ __launch_bounds__(64) void scan_kernel(
    const float* __restrict__ dtdu, const float* __restrict__ xdbl,
    const float* __restrict__ A_log, float* __restrict__ ys) {
    int grp = threadIdx.x >> 4;
    int n = threadIdx.x & 15;
    int ch = blockIdx.x * 4 + grp;
    int b = ch >> 10;
    int d = ch & (DI - 1);

    float An2 = -__expf(A_log[d * DS + n]) * 1.4426950408889634f;

    const float2* ddp = (const float2*)(dtdu + ((size_t)b * LL * DI + d) * 2); // +t*DI float2s
    const float2* bcp = (const float2*)(xdbl + (size_t)b * LL * 64 + 32 + 2 * n); // +t*32 float2s
    float* yp = ys + (size_t)b * LL * DI + d;

    float h = 0.f;
    float2 cdd[SU], cbc[SU];
#pragma unroll
    for (int j = 0; j < SU; j++) {
        cdd[j] = __ldg(ddp + (size_t)j * DI);
        cbc[j] = __ldg(bcp + (size_t)j * 32);
    }
    for (int t0 = 0; t0 < LL; t0 += SU) {
        float2 ndd[SU], nbc[SU];
        if (t0 + SU < LL) {
#pragma unroll
            for (int j = 0; j < SU; j++) {
                size_t o = (size_t)(t0 + SU + j);
                ndd[j] = __ldg(ddp + o * DI);
                nbc[j] = __ldg(bcp + o * 32);
            }
        }
#pragma unroll
        for (int j = 0; j < SU; j++) {
            float dA = ex2f(cdd[j].x * An2);
            h = fmaf(dA, h, cdd[j].y * cbc[j].x);
            float p = h * cbc[j].y;
            p += __shfl_xor_sync(0xffffffffu, p, 8, 16);
            p += __shfl_xor_sync(0xffffffffu, p, 4, 16);
            p += __shfl_xor_sync(0xffffffffu, p, 2, 16);
            p += __shfl_xor_sync(0xffffffffu, p, 1, 16);
            if (n == 0) yp[(size_t)(t0 + j) * DI] = p;
        }
#pragma unroll
        for (int j = 0; j < SU; j++) { cdd[j] = ndd[j]; cbc[j] = nbc[j]; }
    }
}

// ------- gate: y = (ys + u*D) * silu(z) -> fp16 ------------------------------
__global__ void gate_kernel(const float* __restrict__ ys, const float* __restrict__ u,
                            const float* __restrict__ xz, const float* __restrict__ Dskip,
                            __half* __restrict__ yh) {
    int idx = blockIdx.x * 256 + threadIdx.x;
    if (idx >= ML * DI) return;
    int d = idx & (DI - 1);
    size_t bl = (size_t)(idx >> 10);
    float z = xz[bl * (2 * DI) + DI + d];
    float y = fmaf(u[idx], Dskip[d], ys[idx]) * siluf(z);
    yh[idx] = __float2half_rn(y);
}

// ---------------- LayerNorm ---------------------------------------
__global__ void ln_kernel(float* __restrict__ io, const float* __restrict__ w,
                          const float* __restrict__ b) {
    __shared__ float ssum[4], ssq[4];
    int row = blockIdx.x;
    float* p = io + (size_t)row * DM;
    int t = threadIdx.x;
    float4 v = ((float4*)p)[t];
    float s = v.x + v.y + v.z + v.w;
    float q = v.x * v.x + v.y * v.y + v.z * v.z + v.w * v.w;
#pragma unroll
    for (int o = 16; o; o >>= 1) {
        s += __shfl_xor_sync(0xffffffffu, s, o);
        q += __shfl_xor_sync(0xffffffffu, q, o);
    }
    if ((t & 31) == 0) { ssum[t >> 5] = s; ssq[t >> 5] = q; }
    __syncthreads();
    s = ssum[0] + ssum[1] + ssum[2] + ssum[3];
    q = ssq[0] + ssq[1] + ssq[2] + ssq[3];
    float mu = s * (1.f / DM);
    float var = q * (1.f / DM) - mu * mu;
    float inv = rsqrtf(var + 1e-5f);
    int c = t * 4;
    float4 o;
    o.x = (v.x - mu) * inv * w[c + 0] + b[c + 0];
    o.y = (v.y - mu) * inv * w[c + 1] + b[c + 1];
    o.z = (v.z - mu) * inv * w[c + 2] + b[c + 2];
    o.w = (v.w - mu) * inv * w[c + 3] + b[c + 3];
    ((float4*)p)[t] = o;
}

// ---------------- launch ------------------------------------------
extern "C" void kernel_launch(void* const* d_in, const int* in_sizes, int n_in,
                              void* d_out, int out_size) {
    const float* x_in      = (const float*)d_in[0];
    const float* in_proj_w = (const float*)d_in[1];
    const float* conv_w    = (const float*)d_in[2];
    const float* conv_b    = (const float*)d_in[3];
    const float* x_proj_w  = (const float*)d_in[4];
    const float* dt_proj_w = (const float*)d_in[5];
    const float* dt_proj_b = (const float*)d_in[6];
    const float* A_log     = (const float*)d_in[7];
    const float* D_skip    = (const float*)d_in[8];
    const float* out_proj_w= (const float*)d_in[9];
    const float* ln_w      = (const float*)d_in[10];
    const float* ln_b      = (const float*)d_in[11];
    float* out = (float*)d_out;

    static float *p_xz=nullptr,*p_xc=nullptr,*p_xdbl=nullptr,*p_dtdu=nullptr,*p_ys=nullptr;
    static __half *p_xh,*p_w1h,*p_uh,*p_wxh,*p_yh,*p_w2h;
    if (!p_xz) {
        cudaGetSymbolAddress((void**)&p_xz, g_xz);
        cudaGetSymbolAddress((void**)&p_xc, g_xc);
        cudaGetSymbolAddress((void**)&p_xdbl, g_xdbl);
        cudaGetSymbolAddress((void**)&p_dtdu, g_dtdu);
        cudaGetSymbolAddress((void**)&p_ys, g_ys);
        cudaGetSymbolAddress((void**)&p_xh, g_xh);
        cudaGetSymbolAddress((void**)&p_w1h, g_w1h);
        cudaGetSymbolAddress((void**)&p_uh, g_uh);
        cudaGetSymbolAddress((void**)&p_wxh, g_wxh);
        cudaGetSymbolAddress((void**)&p_yh, g_yh);
        cudaGetSymbolAddress((void**)&p_w2h, g_w2h);
        cudaFuncSetAttribute(mma_gemm_kernel<128>, cudaFuncAttributeMaxDynamicSharedMemorySize, GSMEM128);
        cudaFuncSetAttribute(mma_gemm_kernel<64>,  cudaFuncAttributeMaxDynamicSharedMemorySize, GSMEM64);
    }

    // 0) fp16 converts of inputs/weights (wx with B/C interleave permutation)
    cvt_half_kernel<<<(ML * DM / 4) / 256, 256>>>(x_in, p_xh, ML * DM / 4);
    cvt_half_kernel<<<(2 * DI * DM / 4) / 256, 256>>>(in_proj_w, p_w1h, 2 * DI * DM / 4);
    cvt_half_wx_kernel<<<(64 * DI / 4) / 256, 256>>>(x_proj_w, p_wxh);
    cvt_half_kernel<<<(DM * DI / 4) / 256, 256>>>(out_proj_w, p_w2h, DM * DI / 4);

    // 1) xz = X @ in_proj_w^T   [8192,2048]  (fp16 HMMA)
    mma_gemm_kernel<128><<<dim3(2 * DI / 128, ML / 128), 256, GSMEM128>>>(
        p_xh, p_w1h, p_xz, DM, 2 * DI);

    // 2) u = silu(conv(x)+b)  (+ fp16 u)
    conv_silu_kernel<<<(ML * DI) / 256, 256>>>(p_xz, conv_w, conv_b, p_xc, p_uh);

    // 3) x_dbl = u @ x_proj_w^T   [8192,64]  (fp16 HMMA, BN=64; B/C interleaved)
    mma_gemm_kernel<64><<<dim3(1, ML / 128), 256, GSMEM64>>>(
        p_uh, p_wxh, p_xdbl, DI, 64);

    // 4) dtdu = (softplus(dt), dt*u) interleaved
    sgemm_dt_kernel<<<dim3(DI / 64, ML / 128), 256>>>(p_xdbl, dt_proj_w, dt_proj_b, p_xc, p_dtdu);

    // 5) selective scan (packed float2 loads)
    scan_kernel<<<BB * DI / 4, 64>>>(p_dtdu, p_xdbl, A_log, p_ys);

    // 6) gate -> fp16 y
    gate_kernel<<<(ML * DI) / 256, 256>>>(p_ys, p_xc, p_xz, D_skip, p_yh);

    // 7) out = y @ out_proj_w^T  (fp16 HMMA)
    mma_gemm_kernel<128><<<dim3(DM / 128, ML / 128), 256, GSMEM128>>>(
        p_yh, p_w2h, out, DI, DM);

    // 8) LayerNorm in place
    ln_kernel<<<ML, 128>>>(out, ln_w, ln_b);
}

// round 9
// speedup vs baseline: 6.4831x; 1.0019x over previous
#include <cuda_runtime.h>
#include <cuda_bf16.h>
#include <cuda_fp16.h>
#include <cstdint>
#include <cstddef>

// Problem constants
#define BB 4
#define LL 2048
#define DM 512
#define DI 1024            // D_INNER
#define DS 16              // D_STATE
#define DTR 32             // DT_RANK
#define ML (BB*LL)         // 8192 rows

// ---------------- scratch (no allocations allowed) ----------------
__device__ float g_xz  [(size_t)ML * 2 * DI];
__device__ float g_xc  [(size_t)ML * DI];
__device__ float g_xdbl[(size_t)ML * 64];       // cols: 0..31 dt_lr, 32+2n = B_n, 33+2n = C_n
__device__ float g_dtdu[(size_t)ML * DI * 2];   // interleaved (dt, dt*u)
__device__ float g_ys  [(size_t)ML * DI];

__device__ __align__(256) __half g_xh [(size_t)ML * DM];
__device__ __align__(256) __half g_w1h[(size_t)2 * DI * DM];
__device__ __align__(256) __half g_uh [(size_t)ML * DI];
__device__ __align__(256) __half g_wxh[(size_t)64 * DI];
__device__ __align__(256) __half g_yh [(size_t)ML * DI];
__device__ __align__(256) __half g_w2h[(size_t)DM * DI];

// ---------------- PTX helpers (base ISA only) ----------------
__device__ __forceinline__ uint32_t smem_u32(const void* p) {
    uint32_t a;
    asm("{ .reg .u64 t; cvta.to.shared.u64 t, %1; cvt.u32.u64 %0, t; }" : "=r"(a) : "l"(p));
    return a;
}
__device__ __forceinline__ void cp_async16(uint32_t saddr, const void* gaddr) {
    asm volatile("cp.async.cg.shared.global [%0], [%1], 16;" :: "r"(saddr), "l"(gaddr));
}
__device__ __forceinline__ void ldm_x4(uint32_t* r, uint32_t addr) {
    asm volatile("ldmatrix.sync.aligned.m8n8.x4.shared.b16 {%0,%1,%2,%3}, [%4];"
                 : "=r"(r[0]), "=r"(r[1]), "=r"(r[2]), "=r"(r[3]) : "r"(addr));
}
__device__ __forceinline__ void ldm_x2(uint32_t* r, uint32_t addr) {
    asm volatile("ldmatrix.sync.aligned.m8n8.x2.shared.b16 {%0,%1}, [%2];"
                 : "=r"(r[0]), "=r"(r[1]) : "r"(addr));
}
__device__ __forceinline__ void mma_f16(float* d, const uint32_t* a, const uint32_t* b) {
    asm volatile(
        "mma.sync.aligned.m16n8k16.row.col.f32.f16.f16.f32 "
        "{%0,%1,%2,%3}, {%4,%5,%6,%7}, {%8,%9}, {%0,%1,%2,%3};"
        : "+f"(d[0]), "+f"(d[1]), "+f"(d[2]), "+f"(d[3])
        : "r"(a[0]), "r"(a[1]), "r"(a[2]), "r"(a[3]), "r"(b[0]), "r"(b[1]));
}
__device__ __forceinline__ float ex2f(float x) {
    float y;
    asm("ex2.approx.f32 %0, %1;" : "=f"(y) : "f"(x));
    return y;
}
// XOR swizzle for 64B rows: conflict-free for 16B cp.async writes + ldmatrix
__device__ __forceinline__ uint32_t sw64(uint32_t o) { return o ^ ((o >> 3) & 0x30); }

// ---------------- math helpers ----------------
__device__ __forceinline__ float softplusf(float x) {
    return (x > 20.f) ? x : log1pf(__expf(x));
}
__device__ __forceinline__ float siluf(float x) {
    return x * __frcp_rn(1.f + __expf(-x));
}

// ---------------- fp32 -> fp16 convert -----------------------------
__global__ void cvt_half_kernel(const float* __restrict__ x, __half* __restrict__ h, int n4) {
    int i = blockIdx.x * 256 + threadIdx.x;
    if (i >= n4) return;
    float4 v = ((const float4*)x)[i];
    __half2 h0 = __floats2half2_rn(v.x, v.y);
    __half2 h1 = __floats2half2_rn(v.z, v.w);
    ((__half2*)h)[i * 2 + 0] = h0;
    ((__half2*)h)[i * 2 + 1] = h1;
}

// ------- fp32 -> fp16 convert with B/C row interleave for x_proj_w ----------
// src row j -> dst row: j<32 -> j ; 32<=j<48 -> 32+2(j-32) ; 48<=j<64 -> 33+2(j-48)
__global__ void cvt_half_wx_kernel(const float* __restrict__ x, __half* __restrict__ h) {
    int i = blockIdx.x * 256 + threadIdx.x;       // over 64*DI/4 float4s
    if (i >= 64 * DI / 4) return;
    int row = i / (DI / 4);
    int off = i % (DI / 4);
    int dst = (row < 32) ? row : ((row < 48) ? 32 + 2 * (row - 32) : 33 + 2 * (row - 48));
    float4 v = ((const float4*)x)[i];
    __half2 h0 = __floats2half2_rn(v.x, v.y);
    __half2 h1 = __floats2half2_rn(v.z, v.w);
    ((__half2*)(h + (size_t)dst * DI))[off * 2 + 0] = h0;
    ((__half2*)(h + (size_t)dst * DI))[off * 2 + 1] = h1;
}

// ---------------- HMMA fp16 GEMM -----------------------------------
template <int BN>
__global__ __launch_bounds__(256) void mma_gemm_kernel(
    const __half* __restrict__ A, const __half* __restrict__ B,
    float* __restrict__ C, int K, int ldc) {
    constexpr int NWN = (BN == 128) ? 4 : 2;
    constexpr int NWM = 8 / NWN;
    constexpr int MT = (128 / NWM) / 16;
    constexpr int NT = (BN / NWN) / 8;
    constexpr int ATB = 128 * 64;
    constexpr int BTB = BN * 64;
    constexpr int STG = ATB + BTB;
    constexpr int NSEG = (128 + BN) * 4;

    extern __shared__ __align__(128) char smem[];
    const int tid = threadIdx.x;
    const int lane = tid & 31;
    const int wid = tid >> 5;
    const int warp_m = wid / NWN;
    const int warp_n = wid % NWN;
    const int bm = blockIdx.y * 128;
    const int bn = blockIdx.x * BN;

    uint32_t sb = smem_u32(smem);
    const __half* gpa = A + (size_t)bm * K;
    const __half* gpb = B + (size_t)bn * K;

    float acc[MT][NT][4];
#pragma unroll
    for (int i = 0; i < MT; i++)
#pragma unroll
        for (int j = 0; j < NT; j++)
#pragma unroll
            for (int v = 0; v < 4; v++) acc[i][j][v] = 0.f;

    const int nch = K >> 5;

#define GLOAD(stage_, k0_)                                                          \
    {                                                                               \
        _Pragma("unroll")                                                           \
        for (int i = 0; i < NSEG / 256; i++) {                                      \
            int seg = tid + i * 256;                                                \
            int q = seg & 3;                                                        \
            uint32_t soff; const __half* g;                                         \
            if (seg < 512) {                                                        \
                int r_ = seg >> 2;                                                  \
                soff = sw64(r_ * 64 + q * 16);                                      \
                g = gpa + (size_t)r_ * K + (k0_) + q * 8;                           \
            } else {                                                                \
                int r_ = (seg - 512) >> 2;                                          \
                soff = ATB + sw64(r_ * 64 + q * 16);                                \
                g = gpb + (size_t)r_ * K + (k0_) + q * 8;                           \
            }                                                                       \
            cp_async16(sb + (stage_) * STG + soff, g);                              \
        }                                                                           \
        asm volatile("cp.async.commit_group;");                                     \
    }

    GLOAD(0, 0);
    if (nch > 1) GLOAD(1, 32);

    const int arow = warp_m * (MT * 16) + (lane & 15);
    const int acolb = (lane >> 4) * 16;
    const int brow = warp_n * (NT * 8) + (lane & 7);
    const int bcolb = ((lane >> 3) & 1) * 16;

    for (int c = 0; c < nch; c++) {
        const int s = c % 3;
        if (c + 2 < nch) {
            GLOAD((c + 2) % 3, (c + 2) << 5);
            asm volatile("cp.async.wait_group 2;" ::: "memory");
        } else if (c + 1 < nch) {
            asm volatile("cp.async.wait_group 1;" ::: "memory");
        } else {
            asm volatile("cp.async.wait_group 0;" ::: "memory");
        }
        __syncthreads();

        uint32_t base = sb + s * STG;
#pragma unroll
        for (int ks = 0; ks < 2; ks++) {
            uint32_t a_f[MT][4], b_f[NT][2];
#pragma unroll
            for (int im = 0; im < MT; im++) {
                uint32_t off = sw64((arow + im * 16) * 64 + ks * 32 + acolb);
                ldm_x4(a_f[im], base + off);
            }
#pragma unroll
            for (int jn = 0; jn < NT; jn++) {
                uint32_t off = sw64((brow + jn * 8) * 64 + ks * 32 + bcolb);
                ldm_x2(b_f[jn], base + ATB + off);
            }
#pragma unroll
            for (int im = 0; im < MT; im++)
#pragma unroll
                for (int jn = 0; jn < NT; jn++)
                    mma_f16(acc[im][jn], a_f[im], b_f[jn]);
        }
        __syncthreads();
    }
#undef GLOAD

#pragma unroll
    for (int im = 0; im < MT; im++) {
        int r0 = bm + warp_m * (MT * 16) + im * 16 + (lane >> 2);
#pragma unroll
        for (int jn = 0; jn < NT; jn++) {
            int col = bn + warp_n * (NT * 8) + jn * 8 + (lane & 3) * 2;
            float2 v0; v0.x = acc[im][jn][0]; v0.y = acc[im][jn][1];
            float2 v1; v1.x = acc[im][jn][2]; v1.y = acc[im][jn][3];
            *(float2*)(C + (size_t)r0 * ldc + col) = v0;
            *(float2*)(C + (size_t)(r0 + 8) * ldc + col) = v1;
        }
    }
}

#define GSMEM128 (3 * (128 * 64 + 128 * 64))  // 49152
#define GSMEM64  (3 * (128 * 64 + 64 * 64))   // 36864

// ----- dt SGEMM (K=32): dt = softplus(x_dbl[:,0:32] @ dt_proj_w^T + b)
// writes interleaved (dt, dt*u) float2 pairs into dtdu
__global__ void sgemm_dt_kernel(const float* __restrict__ A, const float* __restrict__ W,
                                const float* __restrict__ bias, const float* __restrict__ u,
                                float* __restrict__ dtdu) {
    __shared__ float As[16 * 132];
    __shared__ float Bs[16 * 68];
    const int tid = threadIdx.x;
    const int tx = tid & 15;
    const int ty = tid >> 4;
    const int bm = blockIdx.y * 128;
    const int bn = blockIdx.x * 64;

    const float* Ab = A + (size_t)bm * 64;
    const float* Wb = W + (size_t)bn * DTR;

    float acc[8][4];
#pragma unroll
    for (int i = 0; i < 8; i++)
#pragma unroll
        for (int j = 0; j < 4; j++) acc[i][j] = 0.f;

    for (int k0 = 0; k0 < DTR; k0 += 16) {
#pragma unroll
        for (int i = 0; i < 2; i++) {
            int qid = tid + i * 256;
            int r = qid >> 2, q = qid & 3;
            float4 v = *(const float4*)(Ab + (size_t)r * 64 + k0 + q * 4);
            As[(q * 4 + 0) * 132 + r] = v.x;
            As[(q * 4 + 1) * 132 + r] = v.y;
            As[(q * 4 + 2) * 132 + r] = v.z;
            As[(q * 4 + 3) * 132 + r] = v.w;
        }
        {
            int r = tid >> 2, q = tid & 3;
            float4 v = *(const float4*)(Wb + (size_t)r * DTR + k0 + q * 4);
            Bs[(q * 4 + 0) * 68 + r] = v.x;
            Bs[(q * 4 + 1) * 68 + r] = v.y;
            Bs[(q * 4 + 2) * 68 + r] = v.z;
            Bs[(q * 4 + 3) * 68 + r] = v.w;
        }
        __syncthreads();
#pragma unroll
        for (int k = 0; k < 16; k++) {
            float4 a0 = *(const float4*)(As + k * 132 + ty * 8);
            float4 a1 = *(const float4*)(As + k * 132 + ty * 8 + 4);
            float4 b0 = *(const float4*)(Bs + k * 68 + tx * 4);
            float a[8] = {a0.x, a0.y, a0.z, a0.w, a1.x, a1.y, a1.z, a1.w};
            float bb[4] = {b0.x, b0.y, b0.z, b0.w};
#pragma unroll
            for (int i = 0; i < 8; i++)
#pragma unroll
                for (int j = 0; j < 4; j++) acc[i][j] = fmaf(a[i], bb[j], acc[i][j]);
        }
        __syncthreads();
    }

#pragma unroll
    for (int i = 0; i < 8; i++) {
        int row = bm + ty * 8 + i;
        int col = bn + tx * 4;
        float4 uv = *(const float4*)(u + (size_t)row * DI + col);
        float d0 = softplusf(acc[i][0] + bias[col + 0]);
        float d1 = softplusf(acc[i][1] + bias[col + 1]);
        float d2 = softplusf(acc[i][2] + bias[col + 2]);
        float d3 = softplusf(acc[i][3] + bias[col + 3]);
        float4 o0; o0.x = d0; o0.y = d0 * uv.x; o0.z = d1; o0.w = d1 * uv.y;
        float4 o1; o1.x = d2; o1.y = d2 * uv.z; o1.z = d3; o1.w = d3 * uv.w;
        float* dst = dtdu + (size_t)row * (2 * DI) + 2 * col;
        *(float4*)(dst + 0) = o0;
        *(float4*)(dst + 4) = o1;
    }
}

// ------- depthwise causal conv + bias + SiLU; emits fp32 u AND fp16 u --------
__global__ void conv_silu_kernel(const float* __restrict__ xz, const float* __restrict__ w,
                                 const float* __restrict__ b, float* __restrict__ out,
                                 __half* __restrict__ uh) {
    int idx = blockIdx.x * 256 + threadIdx.x;
    if (idx >= ML * DI) return;
    int d = idx & (DI - 1);
    int bl = idx >> 10;
    int l = bl & (LL - 1);
    float acc = b[d];
#pragma unroll
    for (int k = 0; k < 4; k++) {
        int lk = l - 3 + k;
        if (lk >= 0) acc = fmaf(w[d * 4 + k], xz[(size_t)(bl - 3 + k) * (2 * DI) + d], acc);
    }
    float s = siluf(acc);
    out[idx] = s;
    uh[idx] = __float2half_rn(s);
}

// ------- selective scan: 8 lanes/channel, 2 states/lane, SW-pipelined --------
// warp = 4 channels; B/C pair for both states = one float4; dt/dtu broadcast.
#define SU 8
__global__ __launch_bounds__(64) void scan_kernel(
    const float* __restrict__ dtdu, const float* __restrict__ xdbl,
    const float* __restrict__ A_log, float* __restrict__ ys) {
    int grp = threadIdx.x >> 3;       // 8 channel-groups per 64-thread block
    int sub = threadIdx.x & 7;        // lane within channel (handles states 2sub, 2sub+1)
    int ch = blockIdx.x * 8 + grp;
    int b = ch >> 10;
    int d = ch & (DI - 1);

    const float LOG2E = 1.4426950408889634f;
    float An0 = -__expf(A_log[d * DS + 2 * sub + 0]) * LOG2E;
    float An1 = -__expf(A_log[d * DS + 2 * sub + 1]) * LOG2E;

    const float2* ddp = (const float2*)(dtdu + ((size_t)b * LL * DI + d) * 2);     // +t*DI
    const float4* bcp = (const float4*)(xdbl + (size_t)b * LL * 64 + 32 + 4 * sub); // +t*16
    float* yp = ys + (size_t)b * LL * DI + d;

    float h0 = 0.f, h1 = 0.f;
    float2 cdd[SU]; float4 cbc[SU];
#pragma unroll
    for (int j = 0; j < SU; j++) {
        cdd[j] = __ldg(ddp + (size_t)j * DI);
        cbc[j] = __ldg(bcp + (size_t)j * 16);
    }
    for (int t0 = 0; t0 < LL; t0 += SU) {
        float2 ndd[SU]; float4 nbc[SU];
        if (t0 + SU < LL) {
#pragma unroll
            for (int j = 0; j < SU; j++) {
                size_t o = (size_t)(t0 + SU + j);
                ndd[j] = __ldg(ddp + o * DI);
                nbc[j] = __ldg(bcp + o * 16);
            }
        }
#pragma unroll
        for (int j = 0; j < SU; j++) {
            float dA0 = ex2f(cdd[j].x * An0);
            float dA1 = ex2f(cdd[j].x * An1);
            h0 = fmaf(dA0, h0, cdd[j].y * cbc[j].x);   // B_2s
            h1 = fmaf(dA1, h1, cdd[j].y * cbc[j].z);   // B_2s+1
            float p = fmaf(h1, cbc[j].w, h0 * cbc[j].y);
            p += __shfl_xor_sync(0xffffffffu, p, 4, 8);
            p += __shfl_xor_sync(0xffffffffu, p, 2, 8);
            p += __shfl_xor_sync(0xffffffffu, p, 1, 8);
            if (sub == 0) yp[(size_t)(t0 + j) * DI] = p;
        }
#pragma unroll
        for (int j = 0; j < SU; j++) { cdd[j] = ndd[j]; cbc[j] = nbc[j]; }
    }
}

// ------- gate: y = (ys + u*D) * silu(z) -> fp16 ------------------------------
__global__ void gate_kernel(const float* __restrict__ ys, const float* __restrict__ u,
                            const float* __restrict__ xz, const float* __restrict__ Dskip,
                            __half* __restrict__ yh) {
    int idx = blockIdx.x * 256 + threadIdx.x;
    if (idx >= ML * DI) return;
    int d = idx & (DI - 1);
    size_t bl = (size_t)(idx >> 10);
    float z = xz[bl * (2 * DI) + DI + d];
    float y = fmaf(u[idx], Dskip[d], ys[idx]) * siluf(z);
    yh[idx] = __float2half_rn(y);
}

// ---------------- LayerNorm ---------------------------------------
__global__ void ln_kernel(float* __restrict__ io, const float* __restrict__ w,
                          const float* __restrict__ b) {
    __shared__ float ssum[4], ssq[4];
    int row = blockIdx.x;
    float* p = io + (size_t)row * DM;
    int t = threadIdx.x;
    float4 v = ((float4*)p)[t];
    float s = v.x + v.y + v.z + v.w;
    float q = v.x * v.x + v.y * v.y + v.z * v.z + v.w * v.w;
#pragma unroll
    for (int o = 16; o; o >>= 1) {
        s += __shfl_xor_sync(0xffffffffu, s, o);
        q += __shfl_xor_sync(0xffffffffu, q, o);
    }
    if ((t & 31) == 0) { ssum[t >> 5] = s; ssq[t >> 5] = q; }
    __syncthreads();
    s = ssum[0] + ssum[1] + ssum[2] + ssum[3];
    q = ssq[0] + ssq[1] + ssq[2] + ssq[3];
    float mu = s * (1.f / DM);
    float var = q * (1.f / DM) - mu * mu;
    float inv = rsqrtf(var + 1e-5f);
    int c = t * 4;
    float4 o;
    o.x = (v.x - mu) * inv * w[c + 0] + b[c + 0];
    o.y = (v.y - mu) * inv * w[c + 1] + b[c + 1];
    o.z = (v.z - mu) * inv * w[c + 2] + b[c + 2];
    o.w = (v.w - mu) * inv * w[c + 3] + b[c + 3];
    ((float4*)p)[t] = o;
}

// ---------------- launch ------------------------------------------
extern "C" void kernel_launch(void* const* d_in, const int* in_sizes, int n_in,
                              void* d_out, int out_size) {
    const float* x_in      = (const float*)d_in[0];
    const float* in_proj_w = (const float*)d_in[1];
    const float* conv_w    = (const float*)d_in[2];
    const float* conv_b    = (const float*)d_in[3];
    const float* x_proj_w  = (const float*)d_in[4];
    const float* dt_proj_w = (const float*)d_in[5];
    const float* dt_proj_b = (const float*)d_in[6];
    const float* A_log     = (const float*)d_in[7];
    const float* D_skip    = (const float*)d_in[8];
    const float* out_proj_w= (const float*)d_in[9];
    const float* ln_w      = (const float*)d_in[10];
    const float* ln_b      = (const float*)d_in[11];
    float* out = (float*)d_out;

    static float *p_xz=nullptr,*p_xc=nullptr,*p_xdbl=nullptr,*p_dtdu=nullptr,*p_ys=nullptr;
    static __half *p_xh,*p_w1h,*p_uh,*p_wxh,*p_yh,*p_w2h;
    if (!p_xz) {
        cudaGetSymbolAddress((void**)&p_xz, g_xz);
        cudaGetSymbolAddress((void**)&p_xc, g_xc);
        cudaGetSymbolAddress((void**)&p_xdbl, g_xdbl);
        cudaGetSymbolAddress((void**)&p_dtdu, g_dtdu);
        cudaGetSymbolAddress((void**)&p_ys, g_ys);
        cudaGetSymbolAddress((void**)&p_xh, g_xh);
        cudaGetSymbolAddress((void**)&p_w1h, g_w1h);
        cudaGetSymbolAddress((void**)&p_uh, g_uh);
        cudaGetSymbolAddress((void**)&p_wxh, g_wxh);
        cudaGetSymbolAddress((void**)&p_yh, g_yh);
        cudaGetSymbolAddress((void**)&p_w2h, g_w2h);
        cudaFuncSetAttribute(mma_gemm_kernel<128>, cudaFuncAttributeMaxDynamicSharedMemorySize, GSMEM128);
        cudaFuncSetAttribute(mma_gemm_kernel<64>,  cudaFuncAttributeMaxDynamicSharedMemorySize, GSMEM64);
    }

    // 0) fp16 converts of inputs/weights (wx with B/C interleave permutation)
    cvt_half_kernel<<<(ML * DM / 4) / 256, 256>>>(x_in, p_xh, ML * DM / 4);
    cvt_half_kernel<<<(2 * DI * DM / 4) / 256, 256>>>(in_proj_w, p_w1h, 2 * DI * DM / 4);
    cvt_half_wx_kernel<<<(64 * DI / 4) / 256, 256>>>(x_proj_w, p_wxh);
    cvt_half_kernel<<<(DM * DI / 4) / 256, 256>>>(out_proj_w, p_w2h, DM * DI / 4);

    // 1) xz = X @ in_proj_w^T   [8192,2048]  (fp16 HMMA)
    mma_gemm_kernel<128><<<dim3(2 * DI / 128, ML / 128), 256, GSMEM128>>>(
        p_xh, p_w1h, p_xz, DM, 2 * DI);

    // 2) u = silu(conv(x)+b)  (+ fp16 u)
    conv_silu_kernel<<<(ML * DI) / 256, 256>>>(p_xz, conv_w, conv_b, p_xc, p_uh);

    // 3) x_dbl = u @ x_proj_w^T   [8192,64]  (fp16 HMMA, BN=64; B/C interleaved)
    mma_gemm_kernel<64><<<dim3(1, ML / 128), 256, GSMEM64>>>(
        p_uh, p_wxh, p_xdbl, DI, 64);

    // 4) dtdu = (softplus(dt), dt*u) interleaved
    sgemm_dt_kernel<<<dim3(DI / 64, ML / 128), 256>>>(p_xdbl, dt_proj_w, dt_proj_b, p_xc, p_dtdu);

    // 5) selective scan (8 lanes/channel, 2 states/lane)
    scan_kernel<<<BB * DI / 8, 64>>>(p_dtdu, p_xdbl, A_log, p_ys);

    // 6) gate -> fp16 y
    gate_kernel<<<(ML * DI) / 256, 256>>>(p_ys, p_xc, p_xz, D_skip, p_yh);

    // 7) out = y @ out_proj_w^T  (fp16 HMMA)
    mma_gemm_kernel<128><<<dim3(DM / 128, ML / 128), 256, GSMEM128>>>(
        p_yh, p_w2h, out, DI, DM);

    // 8) LayerNorm in place
    ln_kernel<<<ML, 128>>>(out, ln_w, ln_b);
}